// round 1
// baseline (speedup 1.0000x reference)
#include <cuda_runtime.h>
#include <math.h>

#define C 128
#define Kc 7
#define TILE 64
#define XST 132            // padded smem row stride (floats) to avoid bank conflicts
#define DEPTH 16
#define Bz 4
#define S0 8192

// ---------------- scratch (no allocs allowed) ----------------
__device__ float g_bufA[Bz * S0 * C];          // 16 MB
__device__ float g_bufB[Bz * S0 * C];          // 16 MB
__device__ float g_wdT[DEPTH * Kc * C * C];    // transposed dyn weights [i][k][c][d]
__device__ float g_zf[Bz * 4000];              // final scalar sequence

// smem layouts
#define XS_ROWS_CONV  (TILE + 6)
#define XS_ROWS_CONV0 (2 * TILE + 12)
#define SMEM_CONV  ((XS_ROWS_CONV  * XST + C * C + TILE * XST) * 4)
#define SMEM_CONV0 ((XS_ROWS_CONV0 * XST + C * C + TILE * XST) * 4)

__device__ __forceinline__ float gelu_t(float x) {
    // jax.nn.gelu default (approximate=True, tanh form)
    float x3 = x * x * x;
    return 0.5f * x * (1.0f + tanhf(0.7978845608028654f * (x + 0.044715f * x3)));
}

// ---------------- prep: transpose w_dyn [i][d][c][k] -> [i][k][c][d] ----------------
__global__ void transpose_wd_kernel(const float* __restrict__ w, float* __restrict__ o) {
    int idx = blockIdx.x * blockDim.x + threadIdx.x;   // over DEPTH*C*C, d fastest
    if (idx >= DEPTH * C * C) return;
    int d = idx & (C - 1);
    int c = (idx >> 7) & (C - 1);
    int i = idx >> 14;
    const float* src = w + ((size_t)(i * C + d) * C + c) * Kc;
#pragma unroll
    for (int k = 0; k < Kc; k++)
        o[((size_t)(i * Kc + k) * C + c) * C + d] = src[k];
}

// ---------------- start: z = gelu(ipt @ start_k + start_b) ----------------
__global__ void start_kernel(const float* __restrict__ ipt, const float* __restrict__ sk,
                             const float* __restrict__ sb, float* __restrict__ z) {
    int idx = blockIdx.x * blockDim.x + threadIdx.x;   // Bz*S0*C
    int c = idx & (C - 1);
    int bt = idx >> 7;
    z[idx] = gelu_t(ipt[bt] * sk[c] + sb[c]);
}

// ---------------- stride-1 conv block (blocks 1..15) ----------------
__global__ __launch_bounds__(256) void conv_kernel(
    const float* __restrict__ xin, float* __restrict__ xout,
    int T_in, int T_out,
    const float* __restrict__ wdT,   // [Kc][C][C]  (k, c, d)
    const float* __restrict__ ls, const float* __restrict__ lb,
    const float* __restrict__ pk,    // [C][C] (d, e)
    const float* __restrict__ pb) {
    extern __shared__ float sm[];
    float* xs  = sm;                                  // XS_ROWS_CONV * XST
    float* ws  = xs + XS_ROWS_CONV * XST;             // C*C
    float* yns = ws + C * C;                          // TILE * XST

    const int b  = blockIdx.y;
    const int t0 = blockIdx.x * TILE;
    const float* xb = xin + (size_t)b * T_in * C;
    float* ob = xout + (size_t)b * T_out * C;

    const int tid = threadIdx.x;
    const int tx  = tid & 15;     // d-tile
    const int ty  = tid >> 4;     // t-tile

    // load x rows [t0 .. t0+TILE+5] (clamped)
    for (int i = tid; i < XS_ROWS_CONV * (C / 4); i += 256) {
        int r  = i >> 5;          // C/4 = 32
        int c4 = i & 31;
        int rr = min(t0 + r, T_in - 1);
        float4 v = ((const float4*)(xb + (size_t)rr * C))[c4];
        float* dst = xs + r * XST + c4 * 4;
        dst[0] = v.x; dst[1] = v.y; dst[2] = v.z; dst[3] = v.w;
    }

    float acc[4][8];
#pragma unroll
    for (int it = 0; it < 4; it++)
#pragma unroll
        for (int id = 0; id < 8; id++) acc[it][id] = 0.0f;

    for (int k = 0; k < Kc; k++) {
        __syncthreads();   // ws free (also covers xs load at k=0)
        {
            const float4* src = (const float4*)(wdT + (size_t)k * C * C);
            float4* dst4 = (float4*)ws;
            for (int i = tid; i < C * C / 4; i += 256) dst4[i] = src[i];
        }
        __syncthreads();

        float w[4][8];
#pragma unroll
        for (int it = 0; it < 4; it++)
#pragma unroll
            for (int id = 0; id < 8; id++) w[it][id] = 0.0f;

#pragma unroll 4
        for (int c = 0; c < C; c++) {
            float a[4];
#pragma unroll
            for (int it = 0; it < 4; it++) a[it] = xs[(ty * 4 + it + 6) * XST + c];
            const float4* wr = (const float4*)(ws + c * C + tx * 8);
            float4 b0 = wr[0], b1 = wr[1];
#pragma unroll
            for (int it = 0; it < 4; it++) {
                w[it][0] += a[it] * b0.x; w[it][1] += a[it] * b0.y;
                w[it][2] += a[it] * b0.z; w[it][3] += a[it] * b0.w;
                w[it][4] += a[it] * b1.x; w[it][5] += a[it] * b1.y;
                w[it][6] += a[it] * b1.z; w[it][7] += a[it] * b1.w;
            }
        }
        // fold tap k:  acc += x[t+k, d] * tanh(W)
#pragma unroll
        for (int it = 0; it < 4; it++)
#pragma unroll
            for (int id = 0; id < 8; id++) {
                float xv = xs[(ty * 4 + it + k) * XST + tx * 8 + id];
                acc[it][id] += xv * tanhf(w[it][id]);
            }
    }

    // residual + layernorm
#pragma unroll
    for (int it = 0; it < 4; it++) {
        float s = 0.0f, s2 = 0.0f;
#pragma unroll
        for (int id = 0; id < 8; id++) {
            acc[it][id] += xs[(ty * 4 + it + 6) * XST + tx * 8 + id];
            s += acc[it][id];
            s2 += acc[it][id] * acc[it][id];
        }
#pragma unroll
        for (int o = 8; o >= 1; o >>= 1) {
            s  += __shfl_xor_sync(0xffffffffu, s,  o);
            s2 += __shfl_xor_sync(0xffffffffu, s2, o);
        }
        float m = s * (1.0f / C);
        float v = fmaxf(s2 * (1.0f / C) - m * m, 0.0f);
        float inv = rsqrtf(v + 1e-6f);
#pragma unroll
        for (int id = 0; id < 8; id++) {
            int d = tx * 8 + id;
            yns[(ty * 4 + it) * XST + d] = (acc[it][id] - m) * inv * ls[d] + lb[d];
        }
    }
    __syncthreads();   // yns complete; ws free
    {
        const float4* src = (const float4*)pk;
        float4* dst4 = (float4*)ws;
        for (int i = tid; i < C * C / 4; i += 256) dst4[i] = src[i];
    }
    __syncthreads();

    // pointwise GEMM: g[t,e] = sum_d yn[t,d] * pk[d,e]
    float g[4][8];
#pragma unroll
    for (int it = 0; it < 4; it++)
#pragma unroll
        for (int id = 0; id < 8; id++) g[it][id] = 0.0f;

#pragma unroll 4
    for (int c = 0; c < C; c++) {
        float a[4];
#pragma unroll
        for (int it = 0; it < 4; it++) a[it] = yns[(ty * 4 + it) * XST + c];
        const float4* wr = (const float4*)(ws + c * C + tx * 8);
        float4 b0 = wr[0], b1 = wr[1];
#pragma unroll
        for (int it = 0; it < 4; it++) {
            g[it][0] += a[it] * b0.x; g[it][1] += a[it] * b0.y;
            g[it][2] += a[it] * b0.z; g[it][3] += a[it] * b0.w;
            g[it][4] += a[it] * b1.x; g[it][5] += a[it] * b1.y;
            g[it][6] += a[it] * b1.z; g[it][7] += a[it] * b1.w;
        }
    }

#pragma unroll
    for (int it = 0; it < 4; it++) {
        int t = t0 + ty * 4 + it;
        if (t >= T_out) continue;
        float o[8];
#pragma unroll
        for (int id = 0; id < 8; id++) {
            int d = tx * 8 + id;
            float e = g[it][id] + pb[d];
            o[id] = yns[(ty * 4 + it) * XST + d] + gelu_t(e);
        }
        float4* op = (float4*)(ob + (size_t)t * C + tx * 8);
        op[0] = make_float4(o[0], o[1], o[2], o[3]);
        op[1] = make_float4(o[4], o[5], o[6], o[7]);
    }
}

// ---------------- stride-2 target block (block 0) ----------------
__global__ __launch_bounds__(256) void conv0_kernel(
    const float* __restrict__ xin, float* __restrict__ xout,
    int T_in, int T_out,
    const float* __restrict__ wdT,
    const float* __restrict__ ls, const float* __restrict__ lb,
    const float* __restrict__ pk, const float* __restrict__ pb) {
    extern __shared__ float sm[];
    float* xs  = sm;                                  // XS_ROWS_CONV0 * XST
    float* ws  = xs + XS_ROWS_CONV0 * XST;            // C*C
    float* yns = ws + C * C;                          // TILE * XST

    const int b  = blockIdx.y;
    const int t0 = blockIdx.x * TILE;
    const float* xb = xin + (size_t)b * T_in * C;
    float* ob = xout + (size_t)b * T_out * C;

    const int tid = threadIdx.x;
    const int tx  = tid & 15;
    const int ty  = tid >> 4;

    // load x rows [2*t0 .. 2*t0 + 2*TILE+11] (clamped)
    for (int i = tid; i < XS_ROWS_CONV0 * (C / 4); i += 256) {
        int r  = i >> 5;
        int c4 = i & 31;
        int rr = min(2 * t0 + r, T_in - 1);
        float4 v = ((const float4*)(xb + (size_t)rr * C))[c4];
        float* dst = xs + r * XST + c4 * 4;
        dst[0] = v.x; dst[1] = v.y; dst[2] = v.z; dst[3] = v.w;
    }

    float acc[4][8];
#pragma unroll
    for (int it = 0; it < 4; it++)
#pragma unroll
        for (int id = 0; id < 8; id++) acc[it][id] = 0.0f;

    for (int k = 0; k < Kc; k++) {
        __syncthreads();
        {
            const float4* src = (const float4*)(wdT + (size_t)k * C * C);
            float4* dst4 = (float4*)ws;
            for (int i = tid; i < C * C / 4; i += 256) dst4[i] = src[i];
        }
        __syncthreads();

#pragma unroll
        for (int s = 0; s < 2; s++) {
            float w[4][8];
#pragma unroll
            for (int it = 0; it < 4; it++)
#pragma unroll
                for (int id = 0; id < 8; id++) w[it][id] = 0.0f;

#pragma unroll 4
            for (int c = 0; c < C; c++) {
                float a[4];
#pragma unroll
                for (int it = 0; it < 4; it++)
                    a[it] = xs[(2 * (ty * 4 + it) + 12 + s) * XST + c];
                const float4* wr = (const float4*)(ws + c * C + tx * 8);
                float4 b0 = wr[0], b1 = wr[1];
#pragma unroll
                for (int it = 0; it < 4; it++) {
                    w[it][0] += a[it] * b0.x; w[it][1] += a[it] * b0.y;
                    w[it][2] += a[it] * b0.z; w[it][3] += a[it] * b0.w;
                    w[it][4] += a[it] * b1.x; w[it][5] += a[it] * b1.y;
                    w[it][6] += a[it] * b1.z; w[it][7] += a[it] * b1.w;
                }
            }
#pragma unroll
            for (int it = 0; it < 4; it++)
#pragma unroll
                for (int id = 0; id < 8; id++) {
                    float xv = xs[(2 * (ty * 4 + it) + 2 * k + s) * XST + tx * 8 + id];
                    acc[it][id] += xv * tanhf(w[it][id]);
                }
        }
    }

    // residual x[12+2t] + layernorm
#pragma unroll
    for (int it = 0; it < 4; it++) {
        float s = 0.0f, s2 = 0.0f;
#pragma unroll
        for (int id = 0; id < 8; id++) {
            acc[it][id] += xs[(2 * (ty * 4 + it) + 12) * XST + tx * 8 + id];
            s += acc[it][id];
            s2 += acc[it][id] * acc[it][id];
        }
#pragma unroll
        for (int o = 8; o >= 1; o >>= 1) {
            s  += __shfl_xor_sync(0xffffffffu, s,  o);
            s2 += __shfl_xor_sync(0xffffffffu, s2, o);
        }
        float m = s * (1.0f / C);
        float v = fmaxf(s2 * (1.0f / C) - m * m, 0.0f);
        float inv = rsqrtf(v + 1e-6f);
#pragma unroll
        for (int id = 0; id < 8; id++) {
            int d = tx * 8 + id;
            yns[(ty * 4 + it) * XST + d] = (acc[it][id] - m) * inv * ls[d] + lb[d];
        }
    }
    __syncthreads();
    {
        const float4* src = (const float4*)pk;
        float4* dst4 = (float4*)ws;
        for (int i = tid; i < C * C / 4; i += 256) dst4[i] = src[i];
    }
    __syncthreads();

    float g[4][8];
#pragma unroll
    for (int it = 0; it < 4; it++)
#pragma unroll
        for (int id = 0; id < 8; id++) g[it][id] = 0.0f;

#pragma unroll 4
    for (int c = 0; c < C; c++) {
        float a[4];
#pragma unroll
        for (int it = 0; it < 4; it++) a[it] = yns[(ty * 4 + it) * XST + c];
        const float4* wr = (const float4*)(ws + c * C + tx * 8);
        float4 b0 = wr[0], b1 = wr[1];
#pragma unroll
        for (int it = 0; it < 4; it++) {
            g[it][0] += a[it] * b0.x; g[it][1] += a[it] * b0.y;
            g[it][2] += a[it] * b0.z; g[it][3] += a[it] * b0.w;
            g[it][4] += a[it] * b1.x; g[it][5] += a[it] * b1.y;
            g[it][6] += a[it] * b1.z; g[it][7] += a[it] * b1.w;
        }
    }

#pragma unroll
    for (int it = 0; it < 4; it++) {
        int t = t0 + ty * 4 + it;
        if (t >= T_out) continue;
        float o[8];
#pragma unroll
        for (int id = 0; id < 8; id++) {
            int d = tx * 8 + id;
            float e = g[it][id] + pb[d];
            o[id] = yns[(ty * 4 + it) * XST + d] + gelu_t(e);
        }
        float4* op = (float4*)(ob + (size_t)t * C + tx * 8);
        op[0] = make_float4(o[0], o[1], o[2], o[3]);
        op[1] = make_float4(o[4], o[5], o[6], o[7]);
    }
}

// ---------------- end: zf = z @ end_k + end_b ----------------
__global__ void end_kernel(const float* __restrict__ z, const float* __restrict__ ek,
                           const float* __restrict__ eb, float* __restrict__ zf, int Tf) {
    int warp = (blockIdx.x * blockDim.x + threadIdx.x) >> 5;
    int lane = threadIdx.x & 31;
    if (warp >= Bz * Tf) return;
    float4 v = ((const float4*)(z + (size_t)warp * C))[lane];
    float4 e = ((const float4*)ek)[lane];
    float s = v.x * e.x + v.y * e.y + v.z * e.z + v.w * e.w;
#pragma unroll
    for (int o = 16; o >= 1; o >>= 1) s += __shfl_xor_sync(0xffffffffu, s, o);
    if (lane == 0) zf[warp] = s + eb[0];
}

// ---------------- final output assembly ----------------
__global__ void final_kernel(const float* __restrict__ foundry, const float* __restrict__ zf,
                             float* __restrict__ out, int out_size, int Tf) {
    int idx = blockIdx.x * blockDim.x + threadIdx.x;
    if (idx >= out_size) return;
    if (idx < Bz * S0) {
        int b = idx >> 13, t = idx & (S0 - 1);
        out[idx] = (t < S0 - 1) ? foundry[(b << 13) + t + 1] : zf[b * Tf + (Tf - 1)];
    } else if (idx < Bz * S0 + Bz * Tf) {
        out[idx] = zf[idx - Bz * S0];
    } else {
        out[idx] = 0.0f;
    }
}

extern "C" void kernel_launch(void* const* d_in, const int* in_sizes, int n_in,
                              void* d_out, int out_size) {
    const float* foundry = (const float*)d_in[0];
    const float* ipt     = (const float*)d_in[1];
    const float* start_k = (const float*)d_in[2];
    const float* start_b = (const float*)d_in[3];
    const float* w_dyn   = (const float*)d_in[4];
    const float* ln_s    = (const float*)d_in[5];
    const float* ln_b    = (const float*)d_in[6];
    const float* pw_k    = (const float*)d_in[7];
    const float* pw_b    = (const float*)d_in[8];
    const float* end_k   = (const float*)d_in[9];
    const float* end_b   = (const float*)d_in[10];
    float* out = (float*)d_out;

    float *pA, *pB, *pW, *pZ;
    cudaGetSymbolAddress((void**)&pA, g_bufA);
    cudaGetSymbolAddress((void**)&pB, g_bufB);
    cudaGetSymbolAddress((void**)&pW, g_wdT);
    cudaGetSymbolAddress((void**)&pZ, g_zf);

    cudaFuncSetAttribute(conv_kernel,  cudaFuncAttributeMaxDynamicSharedMemorySize, SMEM_CONV);
    cudaFuncSetAttribute(conv0_kernel, cudaFuncAttributeMaxDynamicSharedMemorySize, SMEM_CONV0);

    transpose_wd_kernel<<<(DEPTH * C * C + 255) / 256, 256>>>(w_dyn, pW);
    start_kernel<<<(Bz * S0 * C) / 256, 256>>>(ipt, start_k, start_b, pA);

    // block 0: stride-2 target block, 8192 -> 4090
    int T = S0;
    int T2 = (S0 - 2 * Kc) / 2 + 1;   // 4090
    conv0_kernel<<<dim3((T2 + TILE - 1) / TILE, Bz), 256, SMEM_CONV0>>>(
        pA, pB, T, T2, pW, ln_s, ln_b, pw_k, pw_b);

    float* src = pB;
    float* dst = pA;
    int Tc = T2;
    for (int i = 1; i < DEPTH; i++) {
        int To = Tc - (Kc - 1);
        conv_kernel<<<dim3((To + TILE - 1) / TILE, Bz), 256, SMEM_CONV>>>(
            src, dst, Tc, To,
            pW + (size_t)i * Kc * C * C,
            ln_s + i * C, ln_b + i * C,
            pw_k + (size_t)i * C * C, pw_b + i * C);
        float* tmp = src; src = dst; dst = tmp;
        Tc = To;
    }
    // Tc == 4000, result in src

    int warps = Bz * Tc;
    end_kernel<<<(warps * 32 + 255) / 256, 256>>>(src, end_k, end_b, pZ, Tc);
    final_kernel<<<(out_size + 255) / 256, 256>>>(foundry, pZ, out, out_size, Tc);
}

// round 2
// speedup vs baseline: 1.1592x; 1.1592x over previous
#include <cuda_runtime.h>
#include <math.h>

#define C 128
#define Kc 7
#define TILE 64
#define XST 132            // padded smem row stride (floats)
#define DEPTH 16
#define Bz 4
#define S0 8192

// ---------------- scratch (no allocs allowed) ----------------
__device__ float g_bufA[Bz * S0 * C];
__device__ float g_bufB[Bz * S0 * C];
__device__ float g_wdT[DEPTH * Kc * C * C];    // [i][k][c][d]
__device__ float g_zf[Bz * 4000];

__device__ __forceinline__ float fast_tanh(float x) {
    return __fdividef(2.0f, 1.0f + __expf(-2.0f * x)) - 1.0f;
}
__device__ __forceinline__ float gelu_t(float x) {
    // 0.5x(1+tanh(u)) == x / (1 + exp(-2u))
    float u = 0.7978845608028654f * (x + 0.044715f * x * x * x);
    return __fdividef(x, 1.0f + __expf(-2.0f * u));
}

// ---------------- prep: transpose w_dyn [i][d][c][k] -> [i][k][c][d] ----------------
__global__ void transpose_wd_kernel(const float* __restrict__ w, float* __restrict__ o) {
    int idx = blockIdx.x * blockDim.x + threadIdx.x;
    if (idx >= DEPTH * C * C) return;
    int d = idx & (C - 1);
    int c = (idx >> 7) & (C - 1);
    int i = idx >> 14;
    const float* src = w + ((size_t)(i * C + d) * C + c) * Kc;
#pragma unroll
    for (int k = 0; k < Kc; k++)
        o[((size_t)(i * Kc + k) * C + c) * C + d] = src[k];
}

// ---------------- start: z = gelu(ipt @ start_k + start_b) ----------------
__global__ void start_kernel(const float* __restrict__ ipt, const float* __restrict__ sk,
                             const float* __restrict__ sb, float* __restrict__ z) {
    int idx = blockIdx.x * blockDim.x + threadIdx.x;
    int c = idx & (C - 1);
    int bt = idx >> 7;
    z[idx] = gelu_t(ipt[bt] * sk[c] + sb[c]);
}

// ---------------- fused conv block, templated on stride (NS=1 normal, NS=2 target) ----------------
// 256 threads: tx = tid&15 (d-tile of 8), ty = tid>>4 (t-tile of 4). Register tile 4t x 8d.
// Weights streamed in 32-c chunks (16KB) through a cp.async double buffer.
// Chunk stream: NS*28 weight chunks (s-pass, k, c-quarter) then 4 pointwise chunks.
template <int NS>
__global__ __launch_bounds__(256, 2) void conv_tpl(
    const float* __restrict__ xin, float* __restrict__ xout,
    int T_in, int T_out,
    const float* __restrict__ wdT,   // [Kc][C][C]
    const float* __restrict__ ls, const float* __restrict__ lb,
    const float* __restrict__ pk,    // [C][C]
    const float* __restrict__ pb) {
    constexpr int XROWS = (NS == 1) ? (TILE + 6) : (2 * TILE + 12);
    constexpr int NWCH = NS * 28;
    constexpr int NCH = NWCH + 4;

    extern __shared__ float sm[];
    float* xs = sm;                       // XROWS * XST  (rows 0..63 become yns later)
    float* wbuf = sm + XROWS * XST;       // 2 * 32 * C

    const int b  = blockIdx.y;
    const int t0 = blockIdx.x * TILE;
    const float* xb = xin + (size_t)b * T_in * C;
    float* ob = xout + (size_t)b * T_out * C;

    const int tid = threadIdx.x;
    const int tx  = tid & 15;
    const int ty  = tid >> 4;

    // load input rows (clamped)
    for (int i = tid; i < XROWS * (C / 4); i += 256) {
        int r  = i >> 5;
        int c4 = i & 31;
        int rr = min(NS * t0 + r, T_in - 1);
        float4 v = ((const float4*)(xb + (size_t)rr * C))[c4];
        *(float4*)&xs[r * XST + c4 * 4] = v;
    }

    // cp.async prefetch of chunk q into wbuf[q&1]
    auto prefetch = [&](int q) {
        const float* src;
        if (q < NWCH) {
            int sub = q % 28;
            src = wdT + (size_t)(sub >> 2) * (C * C) + (sub & 3) * 32 * C;
        } else {
            src = pk + (size_t)(q - NWCH) * 32 * C;
        }
        unsigned da = (unsigned)__cvta_generic_to_shared(wbuf + (q & 1) * 32 * C) + tid * 16;
        const float* s4 = src + tid * 4;
#pragma unroll
        for (int j = 0; j < 4; j++)
            asm volatile("cp.async.cg.shared.global [%0], [%1], 16;"
                         :: "r"(da + j * 4096), "l"(s4 + j * 1024));
    };

    float acc[4][8];
#pragma unroll
    for (int it = 0; it < 4; it++)
#pragma unroll
        for (int id = 0; id < 8; id++) acc[it][id] = 0.0f;
    float w[4][8];

    prefetch(0);
    asm volatile("cp.async.commit_group;");

    for (int q = 0; q < NCH; q++) {
        __syncthreads();                 // prev chunk fully consumed; (q==0: xs stores done)

        if (q == NWCH) {
            // acc currently holds layernormed y; publish to smem rows 0..63, reuse acc as pw accum
#pragma unroll
            for (int it = 0; it < 4; it++) {
                *(float4*)&xs[(ty * 4 + it) * XST + tx * 8] =
                    make_float4(acc[it][0], acc[it][1], acc[it][2], acc[it][3]);
                *(float4*)&xs[(ty * 4 + it) * XST + tx * 8 + 4] =
                    make_float4(acc[it][4], acc[it][5], acc[it][6], acc[it][7]);
#pragma unroll
                for (int id = 0; id < 8; id++) acc[it][id] = 0.0f;
            }
        }

        if (q + 1 < NCH) prefetch(q + 1);
        asm volatile("cp.async.commit_group;");
        asm volatile("cp.async.wait_group 1;");
        __syncthreads();                 // chunk q (and yns write) visible

        const float* wb = wbuf + (q & 1) * 32 * C;

        if (q < NWCH) {
            const int sub = q % 28;
            const int kk = sub >> 2;
            const int cp = sub & 3;
            const int sph = (NS == 2) ? (q / 28) : 0;

            if (cp == 0) {
#pragma unroll
                for (int it = 0; it < 4; it++)
#pragma unroll
                    for (int id = 0; id < 8; id++) w[it][id] = 0.0f;
            }

            int ar[4];
#pragma unroll
            for (int it = 0; it < 4; it++)
                ar[it] = (NS == 1) ? (ty * 4 + it + 6) : (2 * (ty * 4 + it) + 12 + sph);

#pragma unroll
            for (int cq = 0; cq < 8; cq++) {
                float4 a4[4];
#pragma unroll
                for (int it = 0; it < 4; it++)
                    a4[it] = *(const float4*)&xs[ar[it] * XST + cp * 32 + cq * 4];
#pragma unroll
                for (int j = 0; j < 4; j++) {
                    const float* wr = wb + (cq * 4 + j) * C + tx * 8;
                    float4 b0 = *(const float4*)wr;
                    float4 b1 = *(const float4*)(wr + 4);
#pragma unroll
                    for (int it = 0; it < 4; it++) {
                        float av = (j == 0) ? a4[it].x : (j == 1) ? a4[it].y
                                 : (j == 2) ? a4[it].z : a4[it].w;
                        w[it][0] += av * b0.x; w[it][1] += av * b0.y;
                        w[it][2] += av * b0.z; w[it][3] += av * b0.w;
                        w[it][4] += av * b1.x; w[it][5] += av * b1.y;
                        w[it][6] += av * b1.z; w[it][7] += av * b1.w;
                    }
                }
            }

            if (cp == 3) {
                // fold tap (kk, sph): acc += x[tap row, d] * tanh(w)
#pragma unroll
                for (int it = 0; it < 4; it++) {
                    int fr = (NS == 1) ? (ty * 4 + it + kk)
                                       : (2 * (ty * 4 + it) + 2 * kk + sph);
                    float4 xa = *(const float4*)&xs[fr * XST + tx * 8];
                    float4 xc = *(const float4*)&xs[fr * XST + tx * 8 + 4];
                    acc[it][0] += xa.x * fast_tanh(w[it][0]);
                    acc[it][1] += xa.y * fast_tanh(w[it][1]);
                    acc[it][2] += xa.z * fast_tanh(w[it][2]);
                    acc[it][3] += xa.w * fast_tanh(w[it][3]);
                    acc[it][4] += xc.x * fast_tanh(w[it][4]);
                    acc[it][5] += xc.y * fast_tanh(w[it][5]);
                    acc[it][6] += xc.z * fast_tanh(w[it][6]);
                    acc[it][7] += xc.w * fast_tanh(w[it][7]);
                }
            }

            if (q == NWCH - 1) {
                // residual + layernorm, result kept in acc
#pragma unroll
                for (int it = 0; it < 4; it++) {
                    int rr = (NS == 1) ? (ty * 4 + it + 6) : (2 * (ty * 4 + it) + 12);
                    float4 xa = *(const float4*)&xs[rr * XST + tx * 8];
                    float4 xc = *(const float4*)&xs[rr * XST + tx * 8 + 4];
                    acc[it][0] += xa.x; acc[it][1] += xa.y;
                    acc[it][2] += xa.z; acc[it][3] += xa.w;
                    acc[it][4] += xc.x; acc[it][5] += xc.y;
                    acc[it][6] += xc.z; acc[it][7] += xc.w;
                    float su = 0.0f, s2 = 0.0f;
#pragma unroll
                    for (int id = 0; id < 8; id++) {
                        su += acc[it][id];
                        s2 += acc[it][id] * acc[it][id];
                    }
#pragma unroll
                    for (int o = 8; o >= 1; o >>= 1) {
                        su += __shfl_xor_sync(0xffffffffu, su, o);
                        s2 += __shfl_xor_sync(0xffffffffu, s2, o);
                    }
                    float m = su * (1.0f / C);
                    float v = fmaxf(s2 * (1.0f / C) - m * m, 0.0f);
                    float inv = rsqrtf(v + 1e-6f);
#pragma unroll
                    for (int id = 0; id < 8; id++) {
                        int d = tx * 8 + id;
                        acc[it][id] = (acc[it][id] - m) * inv * ls[d] + lb[d];
                    }
                }
            }
        } else {
            // pointwise GEMM chunk: acc += yns[t, c] * pk[c, d]
            const int cp = q - NWCH;
#pragma unroll
            for (int cq = 0; cq < 8; cq++) {
                float4 a4[4];
#pragma unroll
                for (int it = 0; it < 4; it++)
                    a4[it] = *(const float4*)&xs[(ty * 4 + it) * XST + cp * 32 + cq * 4];
#pragma unroll
                for (int j = 0; j < 4; j++) {
                    const float* wr = wb + (cq * 4 + j) * C + tx * 8;
                    float4 b0 = *(const float4*)wr;
                    float4 b1 = *(const float4*)(wr + 4);
#pragma unroll
                    for (int it = 0; it < 4; it++) {
                        float av = (j == 0) ? a4[it].x : (j == 1) ? a4[it].y
                                 : (j == 2) ? a4[it].z : a4[it].w;
                        acc[it][0] += av * b0.x; acc[it][1] += av * b0.y;
                        acc[it][2] += av * b0.z; acc[it][3] += av * b0.w;
                        acc[it][4] += av * b1.x; acc[it][5] += av * b1.y;
                        acc[it][6] += av * b1.z; acc[it][7] += av * b1.w;
                    }
                }
            }
        }
    }

    // epilogue: out = yns + gelu(acc + pb)
#pragma unroll
    for (int it = 0; it < 4; it++) {
        int t = t0 + ty * 4 + it;
        if (t >= T_out) continue;
        float o[8];
#pragma unroll
        for (int id = 0; id < 8; id++) {
            int d = tx * 8 + id;
            float e = acc[it][id] + pb[d];
            o[id] = xs[(ty * 4 + it) * XST + d] + gelu_t(e);
        }
        float4* op = (float4*)(ob + (size_t)t * C + tx * 8);
        op[0] = make_float4(o[0], o[1], o[2], o[3]);
        op[1] = make_float4(o[4], o[5], o[6], o[7]);
    }
}

#define SMEM_NS1 (((TILE + 6) * XST + 2 * 32 * C) * 4)
#define SMEM_NS2 (((2 * TILE + 12) * XST + 2 * 32 * C) * 4)

// ---------------- end: zf = z @ end_k + end_b ----------------
__global__ void end_kernel(const float* __restrict__ z, const float* __restrict__ ek,
                           const float* __restrict__ eb, float* __restrict__ zf, int Tf) {
    int warp = (blockIdx.x * blockDim.x + threadIdx.x) >> 5;
    int lane = threadIdx.x & 31;
    if (warp >= Bz * Tf) return;
    float4 v = ((const float4*)(z + (size_t)warp * C))[lane];
    float4 e = ((const float4*)ek)[lane];
    float s = v.x * e.x + v.y * e.y + v.z * e.z + v.w * e.w;
#pragma unroll
    for (int o = 16; o >= 1; o >>= 1) s += __shfl_xor_sync(0xffffffffu, s, o);
    if (lane == 0) zf[warp] = s + eb[0];
}

// ---------------- final output assembly ----------------
__global__ void final_kernel(const float* __restrict__ foundry, const float* __restrict__ zf,
                             float* __restrict__ out, int out_size, int Tf) {
    int idx = blockIdx.x * blockDim.x + threadIdx.x;
    if (idx >= out_size) return;
    if (idx < Bz * S0) {
        int b = idx >> 13, t = idx & (S0 - 1);
        out[idx] = (t < S0 - 1) ? foundry[(b << 13) + t + 1] : zf[b * Tf + (Tf - 1)];
    } else if (idx < Bz * S0 + Bz * Tf) {
        out[idx] = zf[idx - Bz * S0];
    } else {
        out[idx] = 0.0f;
    }
}

extern "C" void kernel_launch(void* const* d_in, const int* in_sizes, int n_in,
                              void* d_out, int out_size) {
    const float* foundry = (const float*)d_in[0];
    const float* ipt     = (const float*)d_in[1];
    const float* start_k = (const float*)d_in[2];
    const float* start_b = (const float*)d_in[3];
    const float* w_dyn   = (const float*)d_in[4];
    const float* ln_s    = (const float*)d_in[5];
    const float* ln_b    = (const float*)d_in[6];
    const float* pw_k    = (const float*)d_in[7];
    const float* pw_b    = (const float*)d_in[8];
    const float* end_k   = (const float*)d_in[9];
    const float* end_b   = (const float*)d_in[10];
    float* out = (float*)d_out;

    float *pA, *pB, *pW, *pZ;
    cudaGetSymbolAddress((void**)&pA, g_bufA);
    cudaGetSymbolAddress((void**)&pB, g_bufB);
    cudaGetSymbolAddress((void**)&pW, g_wdT);
    cudaGetSymbolAddress((void**)&pZ, g_zf);

    cudaFuncSetAttribute(conv_tpl<1>, cudaFuncAttributeMaxDynamicSharedMemorySize, SMEM_NS1);
    cudaFuncSetAttribute(conv_tpl<2>, cudaFuncAttributeMaxDynamicSharedMemorySize, SMEM_NS2);

    transpose_wd_kernel<<<(DEPTH * C * C + 255) / 256, 256>>>(w_dyn, pW);
    start_kernel<<<(Bz * S0 * C) / 256, 256>>>(ipt, start_k, start_b, pA);

    // block 0: stride-2 target block, 8192 -> 4090
    int T = S0;
    int T2 = (S0 - 2 * Kc) / 2 + 1;   // 4090
    conv_tpl<2><<<dim3((T2 + TILE - 1) / TILE, Bz), 256, SMEM_NS2>>>(
        pA, pB, T, T2, pW, ln_s, ln_b, pw_k, pw_b);

    float* src = pB;
    float* dst = pA;
    int Tc = T2;
    for (int i = 1; i < DEPTH; i++) {
        int To = Tc - (Kc - 1);
        conv_tpl<1><<<dim3((To + TILE - 1) / TILE, Bz), 256, SMEM_NS1>>>(
            src, dst, Tc, To,
            pW + (size_t)i * Kc * C * C,
            ln_s + i * C, ln_b + i * C,
            pw_k + (size_t)i * C * C, pw_b + i * C);
        float* tmp = src; src = dst; dst = tmp;
        Tc = To;
    }

    int warps = Bz * Tc;
    end_kernel<<<(warps * 32 + 255) / 256, 256>>>(src, end_k, end_b, pZ, Tc);
    final_kernel<<<(out_size + 255) / 256, 256>>>(foundry, pZ, out, out_size, Tc);
}

// round 3
// speedup vs baseline: 1.1601x; 1.0007x over previous
#include <cuda_runtime.h>
#include <math.h>

#define C 128
#define Kc 7
#define TILE 64
#define XST 132            // padded smem row stride (floats)
#define DEPTH 16
#define Bz 4
#define S0 8192

// ---------------- scratch (no allocs allowed) ----------------
__device__ float g_bufA[Bz * S0 * C];
__device__ float g_bufB[Bz * S0 * C];
__device__ float g_wdT[DEPTH * Kc * C * C];    // [i][k][c][d]
__device__ float g_zf[Bz * 4000];

__device__ __forceinline__ float fast_tanh(float x) {
    return __fdividef(2.0f, 1.0f + __expf(-2.0f * x)) - 1.0f;
}
__device__ __forceinline__ float gelu_t(float x) {
    // 0.5x(1+tanh(u)) == x / (1 + exp(-2u))
    float u = 0.7978845608028654f * (x + 0.044715f * x * x * x);
    return __fdividef(x, 1.0f + __expf(-2.0f * u));
}

// ---------------- prep: transpose w_dyn [i][d][c][k] -> [i][k][c][d] ----------------
__global__ void transpose_wd_kernel(const float* __restrict__ w, float* __restrict__ o) {
    int idx = blockIdx.x * blockDim.x + threadIdx.x;
    if (idx >= DEPTH * C * C) return;
    int d = idx & (C - 1);
    int c = (idx >> 7) & (C - 1);
    int i = idx >> 14;
    const float* src = w + ((size_t)(i * C + d) * C + c) * Kc;
#pragma unroll
    for (int k = 0; k < Kc; k++)
        o[((size_t)(i * Kc + k) * C + c) * C + d] = src[k];
}

// ---------------- start: z = gelu(ipt @ start_k + start_b) ----------------
__global__ void start_kernel(const float* __restrict__ ipt, const float* __restrict__ sk,
                             const float* __restrict__ sb, float* __restrict__ z) {
    int idx = blockIdx.x * blockDim.x + threadIdx.x;
    int c = idx & (C - 1);
    int bt = idx >> 7;
    z[idx] = gelu_t(ipt[bt] * sk[c] + sb[c]);
}

// ---------------- fused conv block, templated on stride (NS=1 normal, NS=2 target) ----------------
// 256 threads: tx = tid&15 (d-tile of 8), ty = tid>>4 (t-tile of 4). Register tile 4t x 8d.
// Weights streamed in 32-c chunks (16KB) through a cp.async double buffer.
// Chunk stream: NS*28 weight chunks (s-pass, k, c-quarter) then 4 pointwise chunks.
template <int NS>
__global__ __launch_bounds__(256, 2) void conv_tpl(
    const float* __restrict__ xin, float* __restrict__ xout,
    int T_in, int T_out,
    const float* __restrict__ wdT,   // [Kc][C][C]
    const float* __restrict__ ls, const float* __restrict__ lb,
    const float* __restrict__ pk,    // [C][C]
    const float* __restrict__ pb) {
    constexpr int XROWS = (NS == 1) ? (TILE + 6) : (2 * TILE + 12);
    constexpr int NWCH = NS * 28;
    constexpr int NCH = NWCH + 4;

    extern __shared__ float sm[];
    float* xs = sm;                       // XROWS * XST  (rows 0..63 become yns later)
    float* wbuf = sm + XROWS * XST;       // 2 * 32 * C

    const int b  = blockIdx.y;
    const int t0 = blockIdx.x * TILE;
    const float* xb = xin + (size_t)b * T_in * C;
    float* ob = xout + (size_t)b * T_out * C;

    const int tid = threadIdx.x;
    const int tx  = tid & 15;
    const int ty  = tid >> 4;

    // load input rows (clamped)
    for (int i = tid; i < XROWS * (C / 4); i += 256) {
        int r  = i >> 5;
        int c4 = i & 31;
        int rr = min(NS * t0 + r, T_in - 1);
        float4 v = ((const float4*)(xb + (size_t)rr * C))[c4];
        *(float4*)&xs[r * XST + c4 * 4] = v;
    }

    // cp.async prefetch of chunk q into wbuf[q&1]
    auto prefetch = [&](int q) {
        const float* src;
        if (q < NWCH) {
            int sub = q % 28;
            src = wdT + (size_t)(sub >> 2) * (C * C) + (sub & 3) * 32 * C;
        } else {
            src = pk + (size_t)(q - NWCH) * 32 * C;
        }
        unsigned da = (unsigned)__cvta_generic_to_shared(wbuf + (q & 1) * 32 * C) + tid * 16;
        const float* s4 = src + tid * 4;
#pragma unroll
        for (int j = 0; j < 4; j++)
            asm volatile("cp.async.cg.shared.global [%0], [%1], 16;"
                         :: "r"(da + j * 4096), "l"(s4 + j * 1024));
    };

    float acc[4][8];
#pragma unroll
    for (int it = 0; it < 4; it++)
#pragma unroll
        for (int id = 0; id < 8; id++) acc[it][id] = 0.0f;
    float w[4][8];

    prefetch(0);
    asm volatile("cp.async.commit_group;");

    for (int q = 0; q < NCH; q++) {
        __syncthreads();                 // prev chunk fully consumed; (q==0: xs stores done)

        if (q == NWCH) {
            // acc currently holds layernormed y; publish to smem rows 0..63, reuse acc as pw accum
#pragma unroll
            for (int it = 0; it < 4; it++) {
                *(float4*)&xs[(ty * 4 + it) * XST + tx * 8] =
                    make_float4(acc[it][0], acc[it][1], acc[it][2], acc[it][3]);
                *(float4*)&xs[(ty * 4 + it) * XST + tx * 8 + 4] =
                    make_float4(acc[it][4], acc[it][5], acc[it][6], acc[it][7]);
#pragma unroll
                for (int id = 0; id < 8; id++) acc[it][id] = 0.0f;
            }
        }

        if (q + 1 < NCH) prefetch(q + 1);
        asm volatile("cp.async.commit_group;");
        asm volatile("cp.async.wait_group 1;");
        __syncthreads();                 // chunk q (and yns write) visible

        const float* wb = wbuf + (q & 1) * 32 * C;

        if (q < NWCH) {
            const int sub = q % 28;
            const int kk = sub >> 2;
            const int cp = sub & 3;
            const int sph = (NS == 2) ? (q / 28) : 0;

            if (cp == 0) {
#pragma unroll
                for (int it = 0; it < 4; it++)
#pragma unroll
                    for (int id = 0; id < 8; id++) w[it][id] = 0.0f;
            }

            int ar[4];
#pragma unroll
            for (int it = 0; it < 4; it++)
                ar[it] = (NS == 1) ? (ty * 4 + it + 6) : (2 * (ty * 4 + it) + 12 + sph);

#pragma unroll
            for (int cq = 0; cq < 8; cq++) {
                float4 a4[4];
#pragma unroll
                for (int it = 0; it < 4; it++)
                    a4[it] = *(const float4*)&xs[ar[it] * XST + cp * 32 + cq * 4];
#pragma unroll
                for (int j = 0; j < 4; j++) {
                    const float* wr = wb + (cq * 4 + j) * C + tx * 8;
                    float4 b0 = *(const float4*)wr;
                    float4 b1 = *(const float4*)(wr + 4);
#pragma unroll
                    for (int it = 0; it < 4; it++) {
                        float av = (j == 0) ? a4[it].x : (j == 1) ? a4[it].y
                                 : (j == 2) ? a4[it].z : a4[it].w;
                        w[it][0] += av * b0.x; w[it][1] += av * b0.y;
                        w[it][2] += av * b0.z; w[it][3] += av * b0.w;
                        w[it][4] += av * b1.x; w[it][5] += av * b1.y;
                        w[it][6] += av * b1.z; w[it][7] += av * b1.w;
                    }
                }
            }

            if (cp == 3) {
                // fold tap (kk, sph): acc += x[tap row, d] * tanh(w)
#pragma unroll
                for (int it = 0; it < 4; it++) {
                    int fr = (NS == 1) ? (ty * 4 + it + kk)
                                       : (2 * (ty * 4 + it) + 2 * kk + sph);
                    float4 xa = *(const float4*)&xs[fr * XST + tx * 8];
                    float4 xc = *(const float4*)&xs[fr * XST + tx * 8 + 4];
                    acc[it][0] += xa.x * fast_tanh(w[it][0]);
                    acc[it][1] += xa.y * fast_tanh(w[it][1]);
                    acc[it][2] += xa.z * fast_tanh(w[it][2]);
                    acc[it][3] += xa.w * fast_tanh(w[it][3]);
                    acc[it][4] += xc.x * fast_tanh(w[it][4]);
                    acc[it][5] += xc.y * fast_tanh(w[it][5]);
                    acc[it][6] += xc.z * fast_tanh(w[it][6]);
                    acc[it][7] += xc.w * fast_tanh(w[it][7]);
                }
            }

            if (q == NWCH - 1) {
                // residual + layernorm, result kept in acc
#pragma unroll
                for (int it = 0; it < 4; it++) {
                    int rr = (NS == 1) ? (ty * 4 + it + 6) : (2 * (ty * 4 + it) + 12);
                    float4 xa = *(const float4*)&xs[rr * XST + tx * 8];
                    float4 xc = *(const float4*)&xs[rr * XST + tx * 8 + 4];
                    acc[it][0] += xa.x; acc[it][1] += xa.y;
                    acc[it][2] += xa.z; acc[it][3] += xa.w;
                    acc[it][4] += xc.x; acc[it][5] += xc.y;
                    acc[it][6] += xc.z; acc[it][7] += xc.w;
                    float su = 0.0f, s2 = 0.0f;
#pragma unroll
                    for (int id = 0; id < 8; id++) {
                        su += acc[it][id];
                        s2 += acc[it][id] * acc[it][id];
                    }
#pragma unroll
                    for (int o = 8; o >= 1; o >>= 1) {
                        su += __shfl_xor_sync(0xffffffffu, su, o);
                        s2 += __shfl_xor_sync(0xffffffffu, s2, o);
                    }
                    float m = su * (1.0f / C);
                    float v = fmaxf(s2 * (1.0f / C) - m * m, 0.0f);
                    float inv = rsqrtf(v + 1e-6f);
#pragma unroll
                    for (int id = 0; id < 8; id++) {
                        int d = tx * 8 + id;
                        acc[it][id] = (acc[it][id] - m) * inv * ls[d] + lb[d];
                    }
                }
            }
        } else {
            // pointwise GEMM chunk: acc += yns[t, c] * pk[c, d]
            const int cp = q - NWCH;
#pragma unroll
            for (int cq = 0; cq < 8; cq++) {
                float4 a4[4];
#pragma unroll
                for (int it = 0; it < 4; it++)
                    a4[it] = *(const float4*)&xs[(ty * 4 + it) * XST + cp * 32 + cq * 4];
#pragma unroll
                for (int j = 0; j < 4; j++) {
                    const float* wr = wb + (cq * 4 + j) * C + tx * 8;
                    float4 b0 = *(const float4*)wr;
                    float4 b1 = *(const float4*)(wr + 4);
#pragma unroll
                    for (int it = 0; it < 4; it++) {
                        float av = (j == 0) ? a4[it].x : (j == 1) ? a4[it].y
                                 : (j == 2) ? a4[it].z : a4[it].w;
                        acc[it][0] += av * b0.x; acc[it][1] += av * b0.y;
                        acc[it][2] += av * b0.z; acc[it][3] += av * b0.w;
                        acc[it][4] += av * b1.x; acc[it][5] += av * b1.y;
                        acc[it][6] += av * b1.z; acc[it][7] += av * b1.w;
                    }
                }
            }
        }
    }

    // epilogue: out = yns + gelu(acc + pb)
#pragma unroll
    for (int it = 0; it < 4; it++) {
        int t = t0 + ty * 4 + it;
        if (t >= T_out) continue;
        float o[8];
#pragma unroll
        for (int id = 0; id < 8; id++) {
            int d = tx * 8 + id;
            float e = acc[it][id] + pb[d];
            o[id] = xs[(ty * 4 + it) * XST + d] + gelu_t(e);
        }
        float4* op = (float4*)(ob + (size_t)t * C + tx * 8);
        op[0] = make_float4(o[0], o[1], o[2], o[3]);
        op[1] = make_float4(o[4], o[5], o[6], o[7]);
    }
}

#define SMEM_NS1 (((TILE + 6) * XST + 2 * 32 * C) * 4)
#define SMEM_NS2 (((2 * TILE + 12) * XST + 2 * 32 * C) * 4)

// ---------------- end: zf = z @ end_k + end_b ----------------
__global__ void end_kernel(const float* __restrict__ z, const float* __restrict__ ek,
                           const float* __restrict__ eb, float* __restrict__ zf, int Tf) {
    int warp = (blockIdx.x * blockDim.x + threadIdx.x) >> 5;
    int lane = threadIdx.x & 31;
    if (warp >= Bz * Tf) return;
    float4 v = ((const float4*)(z + (size_t)warp * C))[lane];
    float4 e = ((const float4*)ek)[lane];
    float s = v.x * e.x + v.y * e.y + v.z * e.z + v.w * e.w;
#pragma unroll
    for (int o = 16; o >= 1; o >>= 1) s += __shfl_xor_sync(0xffffffffu, s, o);
    if (lane == 0) zf[warp] = s + eb[0];
}

// ---------------- final output assembly ----------------
__global__ void final_kernel(const float* __restrict__ foundry, const float* __restrict__ zf,
                             float* __restrict__ out, int out_size, int Tf) {
    int idx = blockIdx.x * blockDim.x + threadIdx.x;
    if (idx >= out_size) return;
    if (idx < Bz * S0) {
        int b = idx >> 13, t = idx & (S0 - 1);
        out[idx] = (t < S0 - 1) ? foundry[(b << 13) + t + 1] : zf[b * Tf + (Tf - 1)];
    } else if (idx < Bz * S0 + Bz * Tf) {
        out[idx] = zf[idx - Bz * S0];
    } else {
        out[idx] = 0.0f;
    }
}

extern "C" void kernel_launch(void* const* d_in, const int* in_sizes, int n_in,
                              void* d_out, int out_size) {
    const float* foundry = (const float*)d_in[0];
    const float* ipt     = (const float*)d_in[1];
    const float* start_k = (const float*)d_in[2];
    const float* start_b = (const float*)d_in[3];
    const float* w_dyn   = (const float*)d_in[4];
    const float* ln_s    = (const float*)d_in[5];
    const float* ln_b    = (const float*)d_in[6];
    const float* pw_k    = (const float*)d_in[7];
    const float* pw_b    = (const float*)d_in[8];
    const float* end_k   = (const float*)d_in[9];
    const float* end_b   = (const float*)d_in[10];
    float* out = (float*)d_out;

    float *pA, *pB, *pW, *pZ;
    cudaGetSymbolAddress((void**)&pA, g_bufA);
    cudaGetSymbolAddress((void**)&pB, g_bufB);
    cudaGetSymbolAddress((void**)&pW, g_wdT);
    cudaGetSymbolAddress((void**)&pZ, g_zf);

    cudaFuncSetAttribute(conv_tpl<1>, cudaFuncAttributeMaxDynamicSharedMemorySize, SMEM_NS1);
    cudaFuncSetAttribute(conv_tpl<2>, cudaFuncAttributeMaxDynamicSharedMemorySize, SMEM_NS2);

    transpose_wd_kernel<<<(DEPTH * C * C + 255) / 256, 256>>>(w_dyn, pW);
    start_kernel<<<(Bz * S0 * C) / 256, 256>>>(ipt, start_k, start_b, pA);

    // block 0: stride-2 target block, 8192 -> 4090
    int T = S0;
    int T2 = (S0 - 2 * Kc) / 2 + 1;   // 4090
    conv_tpl<2><<<dim3((T2 + TILE - 1) / TILE, Bz), 256, SMEM_NS2>>>(
        pA, pB, T, T2, pW, ln_s, ln_b, pw_k, pw_b);

    float* src = pB;
    float* dst = pA;
    int Tc = T2;
    for (int i = 1; i < DEPTH; i++) {
        int To = Tc - (Kc - 1);
        conv_tpl<1><<<dim3((To + TILE - 1) / TILE, Bz), 256, SMEM_NS1>>>(
            src, dst, Tc, To,
            pW + (size_t)i * Kc * C * C,
            ln_s + i * C, ln_b + i * C,
            pw_k + (size_t)i * C * C, pw_b + i * C);
        float* tmp = src; src = dst; dst = tmp;
        Tc = To;
    }

    int warps = Bz * Tc;
    end_kernel<<<(warps * 32 + 255) / 256, 256>>>(src, end_k, end_b, pZ, Tc);
    final_kernel<<<(out_size + 255) / 256, 256>>>(foundry, pZ, out, out_size, Tc);
}

// round 4
// speedup vs baseline: 1.2062x; 1.0398x over previous
#include <cuda_runtime.h>
#include <math.h>

#define C 128
#define Kc 7
#define TILE 64
#define XST 132            // padded smem row stride (floats)
#define DEPTH 16
#define Bz 4
#define S0 8192

// ---------------- scratch (no allocs allowed) ----------------
__device__ float g_bufA[Bz * S0 * C];
__device__ float g_bufB[Bz * S0 * C];
__device__ float g_wsp[DEPTH * Kc * C * C * 2];   // [i][k][c][d][{hi,lo}] tf32 pairs
__device__ float g_pks[DEPTH * C * C * 2];        // [i][c][d][{hi,lo}]
__device__ float g_zf[Bz * 4000];

__device__ __forceinline__ float fast_tanh(float x) {
    return __fdividef(2.0f, 1.0f + __expf(-2.0f * x)) - 1.0f;
}
__device__ __forceinline__ float gelu_t(float x) {
    float u = 0.7978845608028654f * (x + 0.044715f * x * x * x);
    return __fdividef(x, 1.0f + __expf(-2.0f * u));
}
__device__ __forceinline__ unsigned tf32r(float x) {
    unsigned r; asm("cvt.rna.tf32.f32 %0, %1;" : "=r"(r) : "f"(x)); return r;
}

#define MMA(d, a, b0v, b1v) asm volatile( \
    "mma.sync.aligned.m16n8k8.row.col.f32.tf32.tf32.f32 " \
    "{%0,%1,%2,%3},{%4,%5,%6,%7},{%8,%9},{%0,%1,%2,%3};" \
    : "+f"(d[0]), "+f"(d[1]), "+f"(d[2]), "+f"(d[3]) \
    : "r"(a[0]), "r"(a[1]), "r"(a[2]), "r"(a[3]), "r"(b0v), "r"(b1v))

// ---------------- prep: split w_dyn [i][d][c][k] -> [i][k][c][d][2] tf32 hi/lo ----------------
__global__ void split_wd_kernel(const float* __restrict__ w, float* __restrict__ o) {
    int idx = blockIdx.x * blockDim.x + threadIdx.x;   // dst order [i][k][c][d]
    if (idx >= DEPTH * Kc * C * C) return;
    int d = idx & 127;
    int c = (idx >> 7) & 127;
    int rest = idx >> 14;
    int k = rest % Kc;
    int i = rest / Kc;
    float v = w[(((size_t)i * C + d) * C + c) * Kc + k];
    unsigned h = tf32r(v);
    float hf = __uint_as_float(h);
    unsigned l = tf32r(v - hf);
    o[(size_t)idx * 2]     = hf;
    o[(size_t)idx * 2 + 1] = __uint_as_float(l);
}

__global__ void split_pk_kernel(const float* __restrict__ p, float* __restrict__ o) {
    int idx = blockIdx.x * blockDim.x + threadIdx.x;   // [i][c][d]
    if (idx >= DEPTH * C * C) return;
    float v = p[idx];
    unsigned h = tf32r(v);
    float hf = __uint_as_float(h);
    unsigned l = tf32r(v - hf);
    o[(size_t)idx * 2]     = hf;
    o[(size_t)idx * 2 + 1] = __uint_as_float(l);
}

// ---------------- start: z = gelu(ipt @ start_k + start_b) ----------------
__global__ void start_kernel(const float* __restrict__ ipt, const float* __restrict__ sk,
                             const float* __restrict__ sb, float* __restrict__ z) {
    int idx = blockIdx.x * blockDim.x + threadIdx.x;
    int c = idx & (C - 1);
    int bt = idx >> 7;
    z[idx] = gelu_t(ipt[bt] * sk[c] + sb[c]);
}

// ---------------- fused conv block on tensor cores (NS=1 normal, NS=2 stride-2 target) ----------------
// 256 threads = 8 warps: wm = wid&3 -> rows [16wm,16wm+16), wn = wid>>2 -> cols [64wn, 64wn+64).
// Weight chunks: 32 channels of B as tf32 {hi,lo} float2 rows, padded to 260 floats/row,
// cp.async double-buffered. 3xTF32 mma for fp32-class accuracy.
template <int NS>
__global__ __launch_bounds__(256, (NS == 1) ? 2 : 1) void conv_tpl(
    const float* __restrict__ xin, float* __restrict__ xout,
    int T_in, int T_out,
    const float* __restrict__ wsp,   // [Kc][C][C][2]
    const float* __restrict__ ls, const float* __restrict__ lb,
    const float* __restrict__ pks,   // [C][C][2]
    const float* __restrict__ pb) {
    constexpr int XROWS = (NS == 1) ? (TILE + 6) : (2 * TILE + 12);
    constexpr int NWCH = NS * 28;            // weight chunks (NS=2 streams each k twice: s=0,1)
    constexpr int NCH = NWCH + 4;            // + pointwise chunks
    constexpr int WBF = 32 * 260;            // floats per weight buffer (padded rows)

    extern __shared__ float sm[];
    float* xs   = sm;                        // XROWS * XST (rows 0..63 reused for LN output)
    float* wbuf = sm + XROWS * XST;          // 2 * WBF
    float* lnS  = wbuf + 2 * WBF;            // [2][64]
    float* lnQ  = lnS + 128;
    float* prm  = lnQ + 128;                 // ls | lb | pb (3*128)

    const int b  = blockIdx.y;
    const int t0 = blockIdx.x * TILE;
    const float* xb = xin + (size_t)b * T_in * C;
    float* ob = xout + (size_t)b * T_out * C;

    const int tid  = threadIdx.x;
    const int lane = tid & 31;
    const int wid  = tid >> 5;
    const int wm   = wid & 3;
    const int wn   = wid >> 2;
    const int gr   = lane >> 2;   // fragment group row 0..7
    const int gq   = lane & 3;    // fragment group col 0..3

    if (tid < 128) { prm[tid] = ls[tid]; prm[128 + tid] = lb[tid]; prm[256 + tid] = pb[tid]; }

    for (int i = tid; i < XROWS * (C / 4); i += 256) {
        int r = i >> 5, c4 = i & 31;
        int rr = min(NS * t0 + r, T_in - 1);
        float4 v = ((const float4*)(xb + (size_t)rr * C))[c4];
        *(float4*)&xs[r * XST + c4 * 4] = v;
    }

    const int row0 = 16 * wm + gr;   // local output row for c0/c1
    const int row1 = row0 + 8;       // for c2/c3

    auto prefetch = [&](int q) {
        const float* src;
        if (q < NWCH) {
            int k  = (NS == 1) ? (q >> 2) : (q >> 3);
            int cp = q & 3;
            src = wsp + ((size_t)k * C + cp * 32) * C * 2;
        } else {
            src = pks + (size_t)(q - NWCH) * 32 * C * 2;
        }
        int row = tid >> 3, seg = tid & 7;
        unsigned da = (unsigned)__cvta_generic_to_shared(wbuf + (q & 1) * WBF)
                      + row * 1040 + seg * 128;
        const float* sp = src + row * 256 + seg * 32;
#pragma unroll
        for (int j = 0; j < 8; j++)
            asm volatile("cp.async.cg.shared.global [%0], [%1], 16;"
                         :: "r"(da + j * 16), "l"(sp + j * 4));
    };

    float Y[8][4], G[8][4];
#pragma unroll
    for (int j = 0; j < 8; j++) { Y[j][0] = Y[j][1] = Y[j][2] = Y[j][3] = 0.0f; }

    prefetch(0);
    asm volatile("cp.async.commit_group;");

    for (int q = 0; q < NCH; q++) {
        __syncthreads();                     // prev chunk consumed (q==0: xs/prm stores done)
        if (q + 1 < NCH) prefetch(q + 1);
        asm volatile("cp.async.commit_group;");
        asm volatile("cp.async.wait_group 1;");
        __syncthreads();                     // chunk q resident

        const float* wb = wbuf + (q & 1) * WBF;
        const int cp = q & 3;
        const bool wphase = (q < NWCH);
        int k = 0, s = 0, arow0, arow1;
        if (wphase) {
            if (NS == 1) { k = q >> 2; arow0 = row0 + 6; arow1 = row1 + 6; }
            else { k = q >> 3; s = (q >> 2) & 1; arow0 = 2 * row0 + 12 + s; arow1 = 2 * row1 + 12 + s; }
            if (cp == 0) {
#pragma unroll
                for (int j = 0; j < 8; j++) { G[j][0] = G[j][1] = G[j][2] = G[j][3] = 0.0f; }
            }
        } else {
            arow0 = row0; arow1 = row1;
            if (q == NWCH) {
#pragma unroll
                for (int j = 0; j < 8; j++) { G[j][0] = G[j][1] = G[j][2] = G[j][3] = 0.0f; }
            }
        }
        const int cb = cp * 32;

#pragma unroll
        for (int ks = 0; ks < 4; ks++) {
            int cc = cb + ks * 8 + gq;
            float af0 = xs[arow0 * XST + cc];
            float af1 = xs[arow1 * XST + cc];
            float af2 = xs[arow0 * XST + cc + 4];
            float af3 = xs[arow1 * XST + cc + 4];
            unsigned ah[4], al[4];
            ah[0] = tf32r(af0); al[0] = tf32r(af0 - __uint_as_float(ah[0]));
            ah[1] = tf32r(af1); al[1] = tf32r(af1 - __uint_as_float(ah[1]));
            ah[2] = tf32r(af2); al[2] = tf32r(af2 - __uint_as_float(ah[2]));
            ah[3] = tf32r(af3); al[3] = tf32r(af3 - __uint_as_float(ah[3]));
            const float* wrow0 = wb + (ks * 8 + gq) * 260;
            const float* wrow1 = wrow0 + 4 * 260;
#pragma unroll
            for (int j = 0; j < 8; j++) {
                int dc = wn * 64 + j * 8 + gr;
                float2 b0 = *(const float2*)(wrow0 + dc * 2);
                float2 b1 = *(const float2*)(wrow1 + dc * 2);
                unsigned b0h = __float_as_uint(b0.x), b0l = __float_as_uint(b0.y);
                unsigned b1h = __float_as_uint(b1.x), b1l = __float_as_uint(b1.y);
                MMA(G[j], ah, b0h, b1h);
                MMA(G[j], ah, b0l, b1l);
                MMA(G[j], al, b0h, b1h);
            }
        }

        if (wphase && cp == 3) {
            // fold tap (k[,s]): Y += x[tap,d] * tanh(G)
            int f0 = (NS == 1) ? (row0 + k) : (2 * row0 + 2 * k + s);
            int f1 = (NS == 1) ? (row1 + k) : (2 * row1 + 2 * k + s);
#pragma unroll
            for (int j = 0; j < 8; j++) {
                int col = wn * 64 + j * 8 + gq * 2;
                float2 x0 = *(const float2*)&xs[f0 * XST + col];
                float2 x1 = *(const float2*)&xs[f1 * XST + col];
                Y[j][0] += x0.x * fast_tanh(G[j][0]);
                Y[j][1] += x0.y * fast_tanh(G[j][1]);
                Y[j][2] += x1.x * fast_tanh(G[j][2]);
                Y[j][3] += x1.y * fast_tanh(G[j][3]);
            }
            if (q == NWCH - 1) {
                // residual + layernorm (cross-warp via lnS/lnQ), LN result -> Y and xs rows 0..63
                int r0 = (NS == 1) ? (row0 + 6) : (2 * row0 + 12);
                int r1 = (NS == 1) ? (row1 + 6) : (2 * row1 + 12);
                float s0 = 0, q0 = 0, s1 = 0, q1 = 0;
#pragma unroll
                for (int j = 0; j < 8; j++) {
                    int col = wn * 64 + j * 8 + gq * 2;
                    float2 x0 = *(const float2*)&xs[r0 * XST + col];
                    float2 x1 = *(const float2*)&xs[r1 * XST + col];
                    Y[j][0] += x0.x; Y[j][1] += x0.y;
                    Y[j][2] += x1.x; Y[j][3] += x1.y;
                    s0 += Y[j][0] + Y[j][1]; q0 += Y[j][0] * Y[j][0] + Y[j][1] * Y[j][1];
                    s1 += Y[j][2] + Y[j][3]; q1 += Y[j][2] * Y[j][2] + Y[j][3] * Y[j][3];
                }
#pragma unroll
                for (int o = 1; o <= 2; o <<= 1) {
                    s0 += __shfl_xor_sync(0xffffffffu, s0, o);
                    q0 += __shfl_xor_sync(0xffffffffu, q0, o);
                    s1 += __shfl_xor_sync(0xffffffffu, s1, o);
                    q1 += __shfl_xor_sync(0xffffffffu, q1, o);
                }
                if (gq == 0) {
                    lnS[wn * 64 + row0] = s0; lnQ[wn * 64 + row0] = q0;
                    lnS[wn * 64 + row1] = s1; lnQ[wn * 64 + row1] = q1;
                }
                __syncthreads();
                float Sa = lnS[row0] + lnS[64 + row0], Qa = lnQ[row0] + lnQ[64 + row0];
                float Sb = lnS[row1] + lnS[64 + row1], Qb = lnQ[row1] + lnQ[64 + row1];
                float m0 = Sa * (1.0f / C), m1 = Sb * (1.0f / C);
                float i0 = rsqrtf(fmaxf(Qa * (1.0f / C) - m0 * m0, 0.0f) + 1e-6f);
                float i1 = rsqrtf(fmaxf(Qb * (1.0f / C) - m1 * m1, 0.0f) + 1e-6f);
#pragma unroll
                for (int j = 0; j < 8; j++) {
                    int col = wn * 64 + j * 8 + gq * 2;
                    Y[j][0] = (Y[j][0] - m0) * i0 * prm[col]     + prm[128 + col];
                    Y[j][1] = (Y[j][1] - m0) * i0 * prm[col + 1] + prm[128 + col + 1];
                    Y[j][2] = (Y[j][2] - m1) * i1 * prm[col]     + prm[128 + col];
                    Y[j][3] = (Y[j][3] - m1) * i1 * prm[col + 1] + prm[128 + col + 1];
                    *(float2*)&xs[row0 * XST + col] = make_float2(Y[j][0], Y[j][1]);
                    *(float2*)&xs[row1 * XST + col] = make_float2(Y[j][2], Y[j][3]);
                }
                // loop-top __syncthreads publishes LN rows before pointwise A-loads
            }
        }
    }

    // epilogue: out = y_ln + gelu(G + pb)
#pragma unroll
    for (int j = 0; j < 8; j++) {
        int col = wn * 64 + j * 8 + gq * 2;
        int tg0 = t0 + row0, tg1 = t0 + row1;
        float o0 = Y[j][0] + gelu_t(G[j][0] + prm[256 + col]);
        float o1 = Y[j][1] + gelu_t(G[j][1] + prm[256 + col + 1]);
        float o2 = Y[j][2] + gelu_t(G[j][2] + prm[256 + col]);
        float o3 = Y[j][3] + gelu_t(G[j][3] + prm[256 + col + 1]);
        if (tg0 < T_out) *(float2*)&ob[(size_t)tg0 * C + col] = make_float2(o0, o1);
        if (tg1 < T_out) *(float2*)&ob[(size_t)tg1 * C + col] = make_float2(o2, o3);
    }
}

#define SMEM_NS1 (((TILE + 6) * XST + 2 * 32 * 260 + 256 + 384) * 4)
#define SMEM_NS2 (((2 * TILE + 12) * XST + 2 * 32 * 260 + 256 + 384) * 4)

// ---------------- end: zf = z @ end_k + end_b ----------------
__global__ void end_kernel(const float* __restrict__ z, const float* __restrict__ ek,
                           const float* __restrict__ eb, float* __restrict__ zf, int Tf) {
    int warp = (blockIdx.x * blockDim.x + threadIdx.x) >> 5;
    int lane = threadIdx.x & 31;
    if (warp >= Bz * Tf) return;
    float4 v = ((const float4*)(z + (size_t)warp * C))[lane];
    float4 e = ((const float4*)ek)[lane];
    float s = v.x * e.x + v.y * e.y + v.z * e.z + v.w * e.w;
#pragma unroll
    for (int o = 16; o >= 1; o >>= 1) s += __shfl_xor_sync(0xffffffffu, s, o);
    if (lane == 0) zf[warp] = s + eb[0];
}

// ---------------- final output assembly ----------------
__global__ void final_kernel(const float* __restrict__ foundry, const float* __restrict__ zf,
                             float* __restrict__ out, int out_size, int Tf) {
    int idx = blockIdx.x * blockDim.x + threadIdx.x;
    if (idx >= out_size) return;
    if (idx < Bz * S0) {
        int b = idx >> 13, t = idx & (S0 - 1);
        out[idx] = (t < S0 - 1) ? foundry[(b << 13) + t + 1] : zf[b * Tf + (Tf - 1)];
    } else if (idx < Bz * S0 + Bz * Tf) {
        out[idx] = zf[idx - Bz * S0];
    } else {
        out[idx] = 0.0f;
    }
}

extern "C" void kernel_launch(void* const* d_in, const int* in_sizes, int n_in,
                              void* d_out, int out_size) {
    const float* foundry = (const float*)d_in[0];
    const float* ipt     = (const float*)d_in[1];
    const float* start_k = (const float*)d_in[2];
    const float* start_b = (const float*)d_in[3];
    const float* w_dyn   = (const float*)d_in[4];
    const float* ln_s    = (const float*)d_in[5];
    const float* ln_b    = (const float*)d_in[6];
    const float* pw_k    = (const float*)d_in[7];
    const float* pw_b    = (const float*)d_in[8];
    const float* end_k   = (const float*)d_in[9];
    const float* end_b   = (const float*)d_in[10];
    float* out = (float*)d_out;

    float *pA, *pB, *pW, *pP, *pZ;
    cudaGetSymbolAddress((void**)&pA, g_bufA);
    cudaGetSymbolAddress((void**)&pB, g_bufB);
    cudaGetSymbolAddress((void**)&pW, g_wsp);
    cudaGetSymbolAddress((void**)&pP, g_pks);
    cudaGetSymbolAddress((void**)&pZ, g_zf);

    cudaFuncSetAttribute(conv_tpl<1>, cudaFuncAttributeMaxDynamicSharedMemorySize, SMEM_NS1);
    cudaFuncSetAttribute(conv_tpl<2>, cudaFuncAttributeMaxDynamicSharedMemorySize, SMEM_NS2);

    split_wd_kernel<<<(DEPTH * Kc * C * C + 255) / 256, 256>>>(w_dyn, pW);
    split_pk_kernel<<<(DEPTH * C * C + 255) / 256, 256>>>(pw_k, pP);
    start_kernel<<<(Bz * S0 * C) / 256, 256>>>(ipt, start_k, start_b, pA);

    // block 0: stride-2 target block, 8192 -> 4090
    int T = S0;
    int T2 = (S0 - 2 * Kc) / 2 + 1;   // 4090
    conv_tpl<2><<<dim3((T2 + TILE - 1) / TILE, Bz), 256, SMEM_NS2>>>(
        pA, pB, T, T2, pW, ln_s, ln_b, pP, pw_b);

    float* src = pB;
    float* dst = pA;
    int Tc = T2;
    for (int i = 1; i < DEPTH; i++) {
        int To = Tc - (Kc - 1);
        conv_tpl<1><<<dim3((To + TILE - 1) / TILE, Bz), 256, SMEM_NS1>>>(
            src, dst, Tc, To,
            pW + (size_t)i * Kc * C * C * 2,
            ln_s + i * C, ln_b + i * C,
            pP + (size_t)i * C * C * 2, pw_b + i * C);
        float* tmp = src; src = dst; dst = tmp;
        Tc = To;
    }

    int warps = Bz * Tc;
    end_kernel<<<(warps * 32 + 255) / 256, 256>>>(src, end_k, end_b, pZ, Tc);
    final_kernel<<<(out_size + 255) / 256, 256>>>(foundry, pZ, out, out_size, Tc);
}

// round 5
// speedup vs baseline: 1.2689x; 1.0520x over previous
#include <cuda_runtime.h>
#include <math.h>

#define C 128
#define Kc 7
#define TILE 64
#define XST 132            // padded smem row stride for x (floats)
#define DEPTH 16
#define Bz 4
#define S0 8192

// ---------------- scratch (no allocs allowed) ----------------
__device__ float g_bufA[Bz * S0 * C];
__device__ float g_bufB[Bz * S0 * C];
__device__ float g_wsp[DEPTH * Kc * C * C * 2];   // [i][k][c][d][{hi,lo}] tf32 pairs
__device__ float g_pks[DEPTH * C * C * 2];        // [i][c][d][{hi,lo}]
__device__ float g_zf[Bz * 4000];

__device__ __forceinline__ float fast_tanh(float x) {
    return __fdividef(2.0f, 1.0f + __expf(-2.0f * x)) - 1.0f;
}
__device__ __forceinline__ float gelu_t(float x) {
    float u = 0.7978845608028654f * (x + 0.044715f * x * x * x);
    return __fdividef(x, 1.0f + __expf(-2.0f * u));
}
__device__ __forceinline__ unsigned tf32r(float x) {
    unsigned r; asm("cvt.rna.tf32.f32 %0, %1;" : "=r"(r) : "f"(x)); return r;
}

#define MMA(d, a, b0v, b1v) asm volatile( \
    "mma.sync.aligned.m16n8k8.row.col.f32.tf32.tf32.f32 " \
    "{%0,%1,%2,%3},{%4,%5,%6,%7},{%8,%9},{%0,%1,%2,%3};" \
    : "+f"(d[0]), "+f"(d[1]), "+f"(d[2]), "+f"(d[3]) \
    : "r"(a[0]), "r"(a[1]), "r"(a[2]), "r"(a[3]), "r"(b0v), "r"(b1v))

// ---------------- prep: split w_dyn [i][d][c][k] -> [i][k][c][d][2] tf32 hi/lo ----------------
__global__ void split_wd_kernel(const float* __restrict__ w, float* __restrict__ o) {
    int idx = blockIdx.x * blockDim.x + threadIdx.x;   // dst order [i][k][c][d]
    if (idx >= DEPTH * Kc * C * C) return;
    int d = idx & 127;
    int c = (idx >> 7) & 127;
    int rest = idx >> 14;
    int k = rest % Kc;
    int i = rest / Kc;
    float v = w[(((size_t)i * C + d) * C + c) * Kc + k];
    unsigned h = tf32r(v);
    float hf = __uint_as_float(h);
    unsigned l = tf32r(v - hf);
    o[(size_t)idx * 2]     = hf;
    o[(size_t)idx * 2 + 1] = __uint_as_float(l);
}

__global__ void split_pk_kernel(const float* __restrict__ p, float* __restrict__ o) {
    int idx = blockIdx.x * blockDim.x + threadIdx.x;   // [i][c][d]
    if (idx >= DEPTH * C * C) return;
    float v = p[idx];
    unsigned h = tf32r(v);
    float hf = __uint_as_float(h);
    unsigned l = tf32r(v - hf);
    o[(size_t)idx * 2]     = hf;
    o[(size_t)idx * 2 + 1] = __uint_as_float(l);
}

// ---------------- start: z = gelu(ipt @ start_k + start_b) ----------------
__global__ void start_kernel(const float* __restrict__ ipt, const float* __restrict__ sk,
                             const float* __restrict__ sb, float* __restrict__ z) {
    int idx = blockIdx.x * blockDim.x + threadIdx.x;
    int c = idx & (C - 1);
    int bt = idx >> 7;
    z[idx] = gelu_t(ipt[bt] * sk[c] + sb[c]);
}

// ---------------- fused conv block on tensor cores (NS=1 normal, NS=2 stride-2 target) ----------------
// 256 threads = 8 warps: wm = wid&3 -> rows [16wm,16wm+16), wn = wid>>2 -> cols [64wn,64wn+64).
// B weights streamed as tf32 {hi,lo} float2 rows padded to WROW=264 floats (conflict-free
// LDS.64: 264 mod 32 == 8), cp.async double-buffered. 3xTF32 mma. NS=2 uses 16-c chunks so
// both variants run 2 CTAs/SM.
template <int NS>
__global__ __launch_bounds__(256, 2) void conv_tpl(
    const float* __restrict__ xin, float* __restrict__ xout,
    int T_in, int T_out,
    const float* __restrict__ wsp,   // [Kc][C][C][2]
    const float* __restrict__ ls, const float* __restrict__ lb,
    const float* __restrict__ pks,   // [C][C][2]
    const float* __restrict__ pb) {
    constexpr int XROWS = (NS == 1) ? (TILE + 6) : (2 * TILE + 12);
    constexpr int CPB   = (NS == 1) ? 32 : 16;        // channels per chunk
    constexpr int NCPP  = C / CPB;                    // chunks per k(-s) pass: 4 / 8
    constexpr int NWCH  = NS * Kc * NCPP;             // 28 / 112
    constexpr int NCH   = NWCH + NCPP;                // + pointwise chunks
    constexpr int WROW  = 264;                        // padded floats per B c-row
    constexpr int WBF   = CPB * WROW;
    constexpr int SEGS  = 256 / CPB;                  // segments per row (8 / 16)
    constexpr int SEGB  = 1024 / SEGS;                // bytes per segment (128 / 64)
    constexpr int NCPA  = SEGB / 16;                  // cp.asyncs per thread (8 / 4)

    extern __shared__ float sm[];
    float* xs   = sm;                        // XROWS * XST (rows 0..63 reused for LN output)
    float* wbuf = sm + XROWS * XST;          // 2 * WBF
    float* lnS  = wbuf + 2 * WBF;            // [2][64]
    float* lnQ  = lnS + 128;
    float* prm  = lnQ + 128;                 // ls | lb | pb (3*128)

    const int b  = blockIdx.y;
    const int t0 = blockIdx.x * TILE;
    const float* xb = xin + (size_t)b * T_in * C;
    float* ob = xout + (size_t)b * T_out * C;

    const int tid  = threadIdx.x;
    const int lane = tid & 31;
    const int wid  = tid >> 5;
    const int wm   = wid & 3;
    const int wn   = wid >> 2;
    const int gr   = lane >> 2;   // fragment group row 0..7
    const int gq   = lane & 3;    // fragment group col 0..3

    if (tid < 128) { prm[tid] = ls[tid]; prm[128 + tid] = lb[tid]; prm[256 + tid] = pb[tid]; }

    for (int i = tid; i < XROWS * (C / 4); i += 256) {
        int r = i >> 5, c4 = i & 31;
        int rr = min(NS * t0 + r, T_in - 1);
        float4 v = ((const float4*)(xb + (size_t)rr * C))[c4];
        *(float4*)&xs[r * XST + c4 * 4] = v;
    }

    const int row0 = 16 * wm + gr;   // local output row for c0/c1
    const int row1 = row0 + 8;       // for c2/c3

    auto prefetch = [&](int q) {
        const float* src;
        if (q < NWCH) {
            int k  = (NS == 1) ? (q >> 2) : (q >> 4);
            int cp = q & (NCPP - 1);
            src = wsp + ((size_t)k * C + cp * CPB) * C * 2;
        } else {
            src = pks + (size_t)(q - NWCH) * CPB * C * 2;
        }
        int row = tid / SEGS, seg = tid % SEGS;
        unsigned da = (unsigned)__cvta_generic_to_shared(wbuf + (q & 1) * WBF)
                      + row * (WROW * 4) + seg * SEGB;
        const float* sp = src + row * 256 + seg * (SEGB / 4);
#pragma unroll
        for (int j = 0; j < NCPA; j++)
            asm volatile("cp.async.cg.shared.global [%0], [%1], 16;"
                         :: "r"(da + j * 16), "l"(sp + j * 4));
    };

    float Y[8][4], G[8][4];
#pragma unroll
    for (int j = 0; j < 8; j++) { Y[j][0] = Y[j][1] = Y[j][2] = Y[j][3] = 0.0f; }

    prefetch(0);
    asm volatile("cp.async.commit_group;");

    for (int q = 0; q < NCH; q++) {
        __syncthreads();                     // prev chunk consumed (q==0: xs/prm stores done)
        if (q + 1 < NCH) prefetch(q + 1);
        asm volatile("cp.async.commit_group;");
        asm volatile("cp.async.wait_group 1;");
        __syncthreads();                     // chunk q resident

        const float* wb = wbuf + (q & 1) * WBF;
        const bool wphase = (q < NWCH);
        int k = 0, s = 0, cp, arow0, arow1;
        if (wphase) {
            cp = q & (NCPP - 1);
            if (NS == 1) { k = q >> 2; arow0 = row0 + 6; arow1 = row1 + 6; }
            else { k = q >> 4; s = (q >> 3) & 1; arow0 = 2 * row0 + 12 + s; arow1 = 2 * row1 + 12 + s; }
            if (cp == 0) {
#pragma unroll
                for (int j = 0; j < 8; j++) { G[j][0] = G[j][1] = G[j][2] = G[j][3] = 0.0f; }
            }
        } else {
            cp = q - NWCH;
            arow0 = row0; arow1 = row1;
            if (q == NWCH) {
#pragma unroll
                for (int j = 0; j < 8; j++) { G[j][0] = G[j][1] = G[j][2] = G[j][3] = 0.0f; }
            }
        }
        const int cb = cp * CPB;

#pragma unroll
        for (int ks = 0; ks < CPB / 8; ks++) {
            int cc = cb + ks * 8 + gq;
            float af0 = xs[arow0 * XST + cc];
            float af1 = xs[arow1 * XST + cc];
            float af2 = xs[arow0 * XST + cc + 4];
            float af3 = xs[arow1 * XST + cc + 4];
            unsigned ah[4], al[4];
            ah[0] = tf32r(af0); al[0] = tf32r(af0 - __uint_as_float(ah[0]));
            ah[1] = tf32r(af1); al[1] = tf32r(af1 - __uint_as_float(ah[1]));
            ah[2] = tf32r(af2); al[2] = tf32r(af2 - __uint_as_float(ah[2]));
            ah[3] = tf32r(af3); al[3] = tf32r(af3 - __uint_as_float(ah[3]));
            const float* wrow0 = wb + (ks * 8 + gq) * WROW;
            const float* wrow1 = wrow0 + 4 * WROW;
#pragma unroll
            for (int j = 0; j < 8; j++) {
                int dc = wn * 64 + j * 8 + gr;
                float2 b0 = *(const float2*)(wrow0 + dc * 2);
                float2 b1 = *(const float2*)(wrow1 + dc * 2);
                unsigned b0h = __float_as_uint(b0.x), b0l = __float_as_uint(b0.y);
                unsigned b1h = __float_as_uint(b1.x), b1l = __float_as_uint(b1.y);
                MMA(G[j], ah, b0h, b1h);
                MMA(G[j], ah, b0l, b1l);
                MMA(G[j], al, b0h, b1h);
            }
        }

        if (wphase && cp == NCPP - 1) {
            // fold tap (k[,s]): Y += x[tap,d] * tanh(G)
            int f0 = (NS == 1) ? (row0 + k) : (2 * row0 + 2 * k + s);
            int f1 = (NS == 1) ? (row1 + k) : (2 * row1 + 2 * k + s);
#pragma unroll
            for (int j = 0; j < 8; j++) {
                int col = wn * 64 + j * 8 + gq * 2;
                float2 x0 = *(const float2*)&xs[f0 * XST + col];
                float2 x1 = *(const float2*)&xs[f1 * XST + col];
                Y[j][0] += x0.x * fast_tanh(G[j][0]);
                Y[j][1] += x0.y * fast_tanh(G[j][1]);
                Y[j][2] += x1.x * fast_tanh(G[j][2]);
                Y[j][3] += x1.y * fast_tanh(G[j][3]);
            }
            if (q == NWCH - 1) {
                // residual + layernorm; inner barrier orders all xs reads before the rewrite
                int r0 = (NS == 1) ? (row0 + 6) : (2 * row0 + 12);
                int r1 = (NS == 1) ? (row1 + 6) : (2 * row1 + 12);
                float s0 = 0, q0 = 0, s1 = 0, q1 = 0;
#pragma unroll
                for (int j = 0; j < 8; j++) {
                    int col = wn * 64 + j * 8 + gq * 2;
                    float2 x0 = *(const float2*)&xs[r0 * XST + col];
                    float2 x1 = *(const float2*)&xs[r1 * XST + col];
                    Y[j][0] += x0.x; Y[j][1] += x0.y;
                    Y[j][2] += x1.x; Y[j][3] += x1.y;
                    s0 += Y[j][0] + Y[j][1]; q0 += Y[j][0] * Y[j][0] + Y[j][1] * Y[j][1];
                    s1 += Y[j][2] + Y[j][3]; q1 += Y[j][2] * Y[j][2] + Y[j][3] * Y[j][3];
                }
#pragma unroll
                for (int o = 1; o <= 2; o <<= 1) {
                    s0 += __shfl_xor_sync(0xffffffffu, s0, o);
                    q0 += __shfl_xor_sync(0xffffffffu, q0, o);
                    s1 += __shfl_xor_sync(0xffffffffu, s1, o);
                    q1 += __shfl_xor_sync(0xffffffffu, q1, o);
                }
                if (gq == 0) {
                    lnS[wn * 64 + row0] = s0; lnQ[wn * 64 + row0] = q0;
                    lnS[wn * 64 + row1] = s1; lnQ[wn * 64 + row1] = q1;
                }
                __syncthreads();
                float Sa = lnS[row0] + lnS[64 + row0], Qa = lnQ[row0] + lnQ[64 + row0];
                float Sb = lnS[row1] + lnS[64 + row1], Qb = lnQ[row1] + lnQ[64 + row1];
                float m0 = Sa * (1.0f / C), m1 = Sb * (1.0f / C);
                float i0 = rsqrtf(fmaxf(Qa * (1.0f / C) - m0 * m0, 0.0f) + 1e-6f);
                float i1 = rsqrtf(fmaxf(Qb * (1.0f / C) - m1 * m1, 0.0f) + 1e-6f);
#pragma unroll
                for (int j = 0; j < 8; j++) {
                    int col = wn * 64 + j * 8 + gq * 2;
                    Y[j][0] = (Y[j][0] - m0) * i0 * prm[col]     + prm[128 + col];
                    Y[j][1] = (Y[j][1] - m0) * i0 * prm[col + 1] + prm[128 + col + 1];
                    Y[j][2] = (Y[j][2] - m1) * i1 * prm[col]     + prm[128 + col];
                    Y[j][3] = (Y[j][3] - m1) * i1 * prm[col + 1] + prm[128 + col + 1];
                    *(float2*)&xs[row0 * XST + col] = make_float2(Y[j][0], Y[j][1]);
                    *(float2*)&xs[row1 * XST + col] = make_float2(Y[j][2], Y[j][3]);
                }
                // loop-top __syncthreads publishes LN rows before pointwise A-loads
            }
        }
    }

    // epilogue: out = y_ln + gelu(G + pb)
#pragma unroll
    for (int j = 0; j < 8; j++) {
        int col = wn * 64 + j * 8 + gq * 2;
        int tg0 = t0 + row0, tg1 = t0 + row1;
        float o0 = Y[j][0] + gelu_t(G[j][0] + prm[256 + col]);
        float o1 = Y[j][1] + gelu_t(G[j][1] + prm[256 + col + 1]);
        float o2 = Y[j][2] + gelu_t(G[j][2] + prm[256 + col]);
        float o3 = Y[j][3] + gelu_t(G[j][3] + prm[256 + col + 1]);
        if (tg0 < T_out) *(float2*)&ob[(size_t)tg0 * C + col] = make_float2(o0, o1);
        if (tg1 < T_out) *(float2*)&ob[(size_t)tg1 * C + col] = make_float2(o2, o3);
    }
}

#define SMEM_NS1 (((TILE + 6) * XST + 2 * 32 * 264 + 256 + 384) * 4)
#define SMEM_NS2 (((2 * TILE + 12) * XST + 2 * 16 * 264 + 256 + 384) * 4)

// ---------------- end: zf = z @ end_k + end_b ----------------
__global__ void end_kernel(const float* __restrict__ z, const float* __restrict__ ek,
                           const float* __restrict__ eb, float* __restrict__ zf, int Tf) {
    int warp = (blockIdx.x * blockDim.x + threadIdx.x) >> 5;
    int lane = threadIdx.x & 31;
    if (warp >= Bz * Tf) return;
    float4 v = ((const float4*)(z + (size_t)warp * C))[lane];
    float4 e = ((const float4*)ek)[lane];
    float s = v.x * e.x + v.y * e.y + v.z * e.z + v.w * e.w;
#pragma unroll
    for (int o = 16; o >= 1; o >>= 1) s += __shfl_xor_sync(0xffffffffu, s, o);
    if (lane == 0) zf[warp] = s + eb[0];
}

// ---------------- final output assembly ----------------
__global__ void final_kernel(const float* __restrict__ foundry, const float* __restrict__ zf,
                             float* __restrict__ out, int out_size, int Tf) {
    int idx = blockIdx.x * blockDim.x + threadIdx.x;
    if (idx >= out_size) return;
    if (idx < Bz * S0) {
        int b = idx >> 13, t = idx & (S0 - 1);
        out[idx] = (t < S0 - 1) ? foundry[(b << 13) + t + 1] : zf[b * Tf + (Tf - 1)];
    } else if (idx < Bz * S0 + Bz * Tf) {
        out[idx] = zf[idx - Bz * S0];
    } else {
        out[idx] = 0.0f;
    }
}

extern "C" void kernel_launch(void* const* d_in, const int* in_sizes, int n_in,
                              void* d_out, int out_size) {
    const float* foundry = (const float*)d_in[0];
    const float* ipt     = (const float*)d_in[1];
    const float* start_k = (const float*)d_in[2];
    const float* start_b = (const float*)d_in[3];
    const float* w_dyn   = (const float*)d_in[4];
    const float* ln_s    = (const float*)d_in[5];
    const float* ln_b    = (const float*)d_in[6];
    const float* pw_k    = (const float*)d_in[7];
    const float* pw_b    = (const float*)d_in[8];
    const float* end_k   = (const float*)d_in[9];
    const float* end_b   = (const float*)d_in[10];
    float* out = (float*)d_out;

    float *pA, *pB, *pW, *pP, *pZ;
    cudaGetSymbolAddress((void**)&pA, g_bufA);
    cudaGetSymbolAddress((void**)&pB, g_bufB);
    cudaGetSymbolAddress((void**)&pW, g_wsp);
    cudaGetSymbolAddress((void**)&pP, g_pks);
    cudaGetSymbolAddress((void**)&pZ, g_zf);

    cudaFuncSetAttribute(conv_tpl<1>, cudaFuncAttributeMaxDynamicSharedMemorySize, SMEM_NS1);
    cudaFuncSetAttribute(conv_tpl<2>, cudaFuncAttributeMaxDynamicSharedMemorySize, SMEM_NS2);

    split_wd_kernel<<<(DEPTH * Kc * C * C + 255) / 256, 256>>>(w_dyn, pW);
    split_pk_kernel<<<(DEPTH * C * C + 255) / 256, 256>>>(pw_k, pP);
    start_kernel<<<(Bz * S0 * C) / 256, 256>>>(ipt, start_k, start_b, pA);

    // block 0: stride-2 target block, 8192 -> 4090
    int T = S0;
    int T2 = (S0 - 2 * Kc) / 2 + 1;   // 4090
    conv_tpl<2><<<dim3((T2 + TILE - 1) / TILE, Bz), 256, SMEM_NS2>>>(
        pA, pB, T, T2, pW, ln_s, ln_b, pP, pw_b);

    float* src = pB;
    float* dst = pA;
    int Tc = T2;
    for (int i = 1; i < DEPTH; i++) {
        int To = Tc - (Kc - 1);
        conv_tpl<1><<<dim3((To + TILE - 1) / TILE, Bz), 256, SMEM_NS1>>>(
            src, dst, Tc, To,
            pW + (size_t)i * Kc * C * C * 2,
            ln_s + i * C, ln_b + i * C,
            pP + (size_t)i * C * C * 2, pw_b + i * C);
        float* tmp = src; src = dst; dst = tmp;
        Tc = To;
    }

    int warps = Bz * Tc;
    end_kernel<<<(warps * 32 + 255) / 256, 256>>>(src, end_k, end_b, pZ, Tc);
    final_kernel<<<(out_size + 255) / 256, 256>>>(foundry, pZ, out, out_size, Tc);
}

// round 6
// speedup vs baseline: 3.4197x; 2.6950x over previous
#include <cuda_runtime.h>
#include <math.h>
#include <stdint.h>

#define C 128
#define Kc 7
#define TILE 64
#define RST 136            // xs row stride in u32 (136 mod 32 == 8 -> conflict-free)
#define DEPTH 16
#define Bz 4
#define S0 8192

// ---------------- scratch (no allocs allowed) ----------------
__device__ float g_bufA[Bz * S0 * C];
__device__ float g_bufB[Bz * S0 * C];
// dyn weights, MMA-native: [i][k][half(0..7)][d(0..127)][g(0..3)][4 u32: bh0,bh1,bl0,bl1]
__device__ unsigned g_whl[DEPTH * Kc * 8 * 128 * 16];
// pointwise, same per-half layout: [i][half][d][g][4]
__device__ unsigned g_phl[DEPTH * 8 * 128 * 16];
__device__ float g_zf[Bz * 4000];

__device__ __forceinline__ float fast_tanh(float x) {
    return __fdividef(2.0f, 1.0f + __expf(-2.0f * x)) - 1.0f;
}
__device__ __forceinline__ float gelu_t(float x) {
    float u = 0.7978845608028654f * (x + 0.044715f * x * x * x);
    return __fdividef(x, 1.0f + __expf(-2.0f * u));
}
// pack two floats to bf16x2: low 16 bits = x0, high = x1
__device__ __forceinline__ unsigned pk2(float x0, float x1) {
    unsigned r; asm("cvt.rn.bf16x2.f32 %0, %1, %2;" : "=r"(r) : "f"(x1), "f"(x0)); return r;
}
__device__ __forceinline__ float bf_lo(unsigned u) { return __uint_as_float(u << 16); }
__device__ __forceinline__ float bf_hi(unsigned u) { return __uint_as_float(u & 0xffff0000u); }

#define MMA16(d, a, b0v, b1v) asm volatile( \
    "mma.sync.aligned.m16n8k16.row.col.f32.bf16.bf16.f32 " \
    "{%0,%1,%2,%3},{%4,%5,%6,%7},{%8,%9},{%0,%1,%2,%3};" \
    : "+f"(d[0]), "+f"(d[1]), "+f"(d[2]), "+f"(d[3]) \
    : "r"(a[0]), "r"(a[1]), "r"(a[2]), "r"(a[3]), "r"(b0v), "r"(b1v))

// ---------------- prep: w_dyn [i][d][c][k] -> bf16 hi/lo MMA layout ----------------
__global__ void split_wd_kernel(const float* __restrict__ w, uint4* __restrict__ o) {
    int idx = blockIdx.x * blockDim.x + threadIdx.x;   // over (i,k,half,d,g)
    if (idx >= DEPTH * Kc * 8 * 128 * 4) return;
    int g = idx & 3;
    int d = (idx >> 2) & 127;
    int half = (idx >> 9) & 7;
    int rest = idx >> 12;
    int k = rest % Kc;
    int i = rest / Kc;
    int c0 = half * 16 + 2 * g;
    const float* wb = w + ((size_t)(i * C + d) * C) * Kc + k;
    float v0 = wb[(size_t)c0 * Kc],       v1 = wb[(size_t)(c0 + 1) * Kc];
    float v8 = wb[(size_t)(c0 + 8) * Kc], v9 = wb[(size_t)(c0 + 9) * Kc];
    unsigned h0 = pk2(v0, v1), h1 = pk2(v8, v9);
    unsigned l0 = pk2(v0 - bf_lo(h0), v1 - bf_hi(h0));
    unsigned l1 = pk2(v8 - bf_lo(h1), v9 - bf_hi(h1));
    o[idx] = make_uint4(h0, h1, l0, l1);
}

__global__ void split_pk_kernel(const float* __restrict__ p, uint4* __restrict__ o) {
    int idx = blockIdx.x * blockDim.x + threadIdx.x;   // over (i,half,d,g)
    if (idx >= DEPTH * 8 * 128 * 4) return;
    int g = idx & 3;
    int d = (idx >> 2) & 127;
    int half = (idx >> 9) & 7;
    int i = idx >> 12;
    int c0 = half * 16 + 2 * g;
    const float* pb = p + (size_t)i * C * C + d;
    float v0 = pb[(size_t)c0 * C],       v1 = pb[(size_t)(c0 + 1) * C];
    float v8 = pb[(size_t)(c0 + 8) * C], v9 = pb[(size_t)(c0 + 9) * C];
    unsigned h0 = pk2(v0, v1), h1 = pk2(v8, v9);
    unsigned l0 = pk2(v0 - bf_lo(h0), v1 - bf_hi(h0));
    unsigned l1 = pk2(v8 - bf_lo(h1), v9 - bf_hi(h1));
    o[idx] = make_uint4(h0, h1, l0, l1);
}

// ---------------- start: z = gelu(ipt @ start_k + start_b) ----------------
__global__ void start_kernel(const float* __restrict__ ipt, const float* __restrict__ sk,
                             const float* __restrict__ sb, float* __restrict__ z) {
    int idx = blockIdx.x * blockDim.x + threadIdx.x;
    int c = idx & (C - 1);
    int bt = idx >> 7;
    z[idx] = gelu_t(ipt[bt] * sk[c] + sb[c]);
}

// ---------------- fused conv block, bf16x3 tensor cores ----------------
// 256 threads = 8 warps: wm = wid&3 -> m16 tile rows [16wm,16wm+16), wn = wid>>2 -> n cols
// [64wn,64wn+64). x lives in smem ONLY as packed bf16 {hi,lo} pairs: xs[row][c2][2] u32,
// row stride RST=136 u32. Weights stream through a cp.async double buffer in the MMA-native
// uint4 layout (one LDS.128 = all 4 B regs). 3 bf16 MMAs (hh, hl, lh) ~ fp32 accuracy.
template <int NS>
__global__ __launch_bounds__(256, 2) void conv_tpl(
    const float* __restrict__ xin, float* __restrict__ xout,
    int T_in, int T_out,
    const unsigned* __restrict__ wsp,   // layer's [Kc][8][128][16] u32
    const float* __restrict__ ls, const float* __restrict__ lb,
    const unsigned* __restrict__ pks,   // layer's [8][128][16] u32
    const float* __restrict__ pb) {
    constexpr int XROWS = (NS == 1) ? (TILE + 6) : (2 * TILE + 12);
    constexpr int CPB   = (NS == 1) ? 64 : 32;        // channels per chunk
    constexpr int HPC   = CPB / 16;                   // 16-chan halves per chunk (4 / 2)
    constexpr int NCPP  = C / CPB;                    // chunks per pass (2 / 4)
    constexpr int NWCH  = NS * Kc * NCPP;             // 14 / 56
    constexpr int NCH   = NWCH + NCPP;
    constexpr int WBF   = HPC * 2048;                 // u32 per buffer (half = 128d*16u32)
    constexpr int NCPA  = HPC * 2;                    // 16B cp.asyncs per thread

    extern __shared__ unsigned smu[];
    unsigned* xs   = smu;                    // XROWS * RST
    unsigned* wbuf = smu + XROWS * RST;      // 2 * WBF
    float* lnS = (float*)(wbuf + 2 * WBF);   // [2][64]
    float* lnQ = lnS + 128;
    float* prm = lnQ + 128;                  // ls | lb | pb

    const int b  = blockIdx.y;
    const int t0 = blockIdx.x * TILE;
    const float* xb = xin + (size_t)b * T_in * C;
    float* ob = xout + (size_t)b * T_out * C;

    const int tid  = threadIdx.x;
    const int lane = tid & 31;
    const int wid  = tid >> 5;
    const int wm   = wid & 3;
    const int wn   = wid >> 2;
    const int gr   = lane >> 2;
    const int gq   = lane & 3;

    if (tid < 128) { prm[tid] = ls[tid]; prm[128 + tid] = lb[tid]; prm[256 + tid] = pb[tid]; }

    // load x rows, convert+pack bf16 hi/lo: one float4 -> uint4 {h0,l0,h1,l1}
    for (int i = tid; i < XROWS * 32; i += 256) {
        int r = i >> 5, c4 = i & 31;
        int rr = min(NS * t0 + r, T_in - 1);
        float4 v = ((const float4*)(xb + (size_t)rr * C))[c4];
        unsigned h0 = pk2(v.x, v.y);
        unsigned l0 = pk2(v.x - bf_lo(h0), v.y - bf_hi(h0));
        unsigned h1 = pk2(v.z, v.w);
        unsigned l1 = pk2(v.z - bf_lo(h1), v.w - bf_hi(h1));
        *(uint4*)&xs[r * RST + c4 * 4] = make_uint4(h0, l0, h1, l1);
    }

    const int row0 = 16 * wm + gr;   // rows of this thread's m16 fragments
    const int row1 = row0 + 8;

    auto prefetch = [&](int q) {
        const unsigned* src;
        if (q < NWCH) {
            int k  = (NS == 1) ? (q >> 1) : (q >> 3);
            int cp = q & (NCPP - 1);
            src = wsp + (size_t)(k * 8 + cp * HPC) * 2048;
        } else {
            src = pks + (size_t)(q - NWCH) * HPC * 2048;
        }
        unsigned da = (unsigned)__cvta_generic_to_shared(wbuf + (q & 1) * WBF) + tid * 16;
        const unsigned* sp = src + tid * 4;
#pragma unroll
        for (int j = 0; j < NCPA; j++)
            asm volatile("cp.async.cg.shared.global [%0], [%1], 16;"
                         :: "r"(da + j * 4096), "l"(sp + j * 1024));
    };

    float Y[8][4], G[8][4];
#pragma unroll
    for (int j = 0; j < 8; j++) { Y[j][0] = Y[j][1] = Y[j][2] = Y[j][3] = 0.0f; }

    prefetch(0);
    asm volatile("cp.async.commit_group;");

    for (int q = 0; q < NCH; q++) {
        __syncthreads();                     // prev chunk consumed (q==0: xs/prm stores done)
        if (q + 1 < NCH) prefetch(q + 1);
        asm volatile("cp.async.commit_group;");
        asm volatile("cp.async.wait_group 1;");
        __syncthreads();                     // chunk q resident

        const unsigned* wb = wbuf + (q & 1) * WBF;
        const bool wphase = (q < NWCH);
        int k = 0, s = 0, cp, arow0;
        if (wphase) {
            cp = q & (NCPP - 1);
            if (NS == 1) { k = q >> 1; arow0 = row0 + 6; }
            else { k = q >> 3; s = (q >> 2) & 1; arow0 = 2 * row0 + 12 + s; }
            if (cp == 0) {
#pragma unroll
                for (int j = 0; j < 8; j++) { G[j][0] = G[j][1] = G[j][2] = G[j][3] = 0.0f; }
            }
        } else {
            cp = q - NWCH;
            arow0 = row0;
            if (q == NWCH) {
#pragma unroll
                for (int j = 0; j < 8; j++) { G[j][0] = G[j][1] = G[j][2] = G[j][3] = 0.0f; }
            }
        }
        const int arow1 = arow0 + ((wphase && NS == 2) ? 16 : 8);
        const int hb0 = cp * HPC;            // global 16-chan half base

#pragma unroll
        for (int h = 0; h < HPC; h++) {
            int c2b = (hb0 + h) * 8;         // c2 base of this 16-chan half
            // A fragments: 4 LDS.64 -> {hi,lo} each
            uint2 p0 = *(const uint2*)&xs[arow0 * RST + (c2b + gq) * 2];
            uint2 p1 = *(const uint2*)&xs[arow1 * RST + (c2b + gq) * 2];
            uint2 p2 = *(const uint2*)&xs[arow0 * RST + (c2b + gq + 4) * 2];
            uint2 p3 = *(const uint2*)&xs[arow1 * RST + (c2b + gq + 4) * 2];
            unsigned ah[4] = { p0.x, p1.x, p2.x, p3.x };
            unsigned al[4] = { p0.y, p1.y, p2.y, p3.y };
            const unsigned* wh = wb + h * 2048;
#pragma unroll
            for (int j = 0; j < 8; j++) {
                int dc = wn * 64 + j * 8 + gr;
                uint4 bv = *(const uint4*)(wh + dc * 16 + gq * 4);  // bh0,bh1,bl0,bl1
                MMA16(G[j], ah, bv.x, bv.y);
                MMA16(G[j], ah, bv.z, bv.w);
                MMA16(G[j], al, bv.x, bv.y);
            }
        }

        if (wphase && cp == NCPP - 1) {
            // fold tap (k[,s]): Y += x[tap,d] * tanh(G)
            int f0 = (NS == 1) ? (row0 + k) : (2 * row0 + 2 * k + s);
            int f1 = (NS == 1) ? (f0 + 8) : (f0 + 16);
#pragma unroll
            for (int j = 0; j < 8; j++) {
                int c2 = wn * 32 + j * 4 + gq;
                uint2 u0 = *(const uint2*)&xs[f0 * RST + c2 * 2];
                uint2 u1 = *(const uint2*)&xs[f1 * RST + c2 * 2];
                Y[j][0] += (bf_lo(u0.x) + bf_lo(u0.y)) * fast_tanh(G[j][0]);
                Y[j][1] += (bf_hi(u0.x) + bf_hi(u0.y)) * fast_tanh(G[j][1]);
                Y[j][2] += (bf_lo(u1.x) + bf_lo(u1.y)) * fast_tanh(G[j][2]);
                Y[j][3] += (bf_hi(u1.x) + bf_hi(u1.y)) * fast_tanh(G[j][3]);
            }
            if (q == NWCH - 1) {
                // residual + layernorm; inner barrier orders all xs reads before rewrite
                int r0 = (NS == 1) ? (row0 + 6) : (2 * row0 + 12);
                int r1 = (NS == 1) ? (r0 + 8) : (r0 + 16);
                float s0 = 0, q0 = 0, s1 = 0, q1 = 0;
#pragma unroll
                for (int j = 0; j < 8; j++) {
                    int c2 = wn * 32 + j * 4 + gq;
                    uint2 u0 = *(const uint2*)&xs[r0 * RST + c2 * 2];
                    uint2 u1 = *(const uint2*)&xs[r1 * RST + c2 * 2];
                    Y[j][0] += bf_lo(u0.x) + bf_lo(u0.y);
                    Y[j][1] += bf_hi(u0.x) + bf_hi(u0.y);
                    Y[j][2] += bf_lo(u1.x) + bf_lo(u1.y);
                    Y[j][3] += bf_hi(u1.x) + bf_hi(u1.y);
                    s0 += Y[j][0] + Y[j][1]; q0 += Y[j][0] * Y[j][0] + Y[j][1] * Y[j][1];
                    s1 += Y[j][2] + Y[j][3]; q1 += Y[j][2] * Y[j][2] + Y[j][3] * Y[j][3];
                }
#pragma unroll
                for (int o = 1; o <= 2; o <<= 1) {
                    s0 += __shfl_xor_sync(0xffffffffu, s0, o);
                    q0 += __shfl_xor_sync(0xffffffffu, q0, o);
                    s1 += __shfl_xor_sync(0xffffffffu, s1, o);
                    q1 += __shfl_xor_sync(0xffffffffu, q1, o);
                }
                if (gq == 0) {
                    lnS[wn * 64 + row0] = s0; lnQ[wn * 64 + row0] = q0;
                    lnS[wn * 64 + row1] = s1; lnQ[wn * 64 + row1] = q1;
                }
                __syncthreads();
                float Sa = lnS[row0] + lnS[64 + row0], Qa = lnQ[row0] + lnQ[64 + row0];
                float Sb = lnS[row1] + lnS[64 + row1], Qb = lnQ[row1] + lnQ[64 + row1];
                float m0 = Sa * (1.0f / C), m1 = Sb * (1.0f / C);
                float i0 = rsqrtf(fmaxf(Qa * (1.0f / C) - m0 * m0, 0.0f) + 1e-6f);
                float i1 = rsqrtf(fmaxf(Qb * (1.0f / C) - m1 * m1, 0.0f) + 1e-6f);
#pragma unroll
                for (int j = 0; j < 8; j++) {
                    int col = wn * 64 + j * 8 + gq * 2;
                    Y[j][0] = (Y[j][0] - m0) * i0 * prm[col]     + prm[128 + col];
                    Y[j][1] = (Y[j][1] - m0) * i0 * prm[col + 1] + prm[128 + col + 1];
                    Y[j][2] = (Y[j][2] - m1) * i1 * prm[col]     + prm[128 + col];
                    Y[j][3] = (Y[j][3] - m1) * i1 * prm[col + 1] + prm[128 + col + 1];
                    int c2 = col >> 1;
                    unsigned h0 = pk2(Y[j][0], Y[j][1]);
                    unsigned l0 = pk2(Y[j][0] - bf_lo(h0), Y[j][1] - bf_hi(h0));
                    unsigned h1 = pk2(Y[j][2], Y[j][3]);
                    unsigned l1 = pk2(Y[j][2] - bf_lo(h1), Y[j][3] - bf_hi(h1));
                    *(uint2*)&xs[row0 * RST + c2 * 2] = make_uint2(h0, l0);
                    *(uint2*)&xs[row1 * RST + c2 * 2] = make_uint2(h1, l1);
                }
                // loop-top __syncthreads publishes LN rows before pointwise A-loads
            }
        }
    }

    // epilogue: out = y_ln + gelu(G + pb)
#pragma unroll
    for (int j = 0; j < 8; j++) {
        int col = wn * 64 + j * 8 + gq * 2;
        int tg0 = t0 + row0, tg1 = t0 + row1;
        float o0 = Y[j][0] + gelu_t(G[j][0] + prm[256 + col]);
        float o1 = Y[j][1] + gelu_t(G[j][1] + prm[256 + col + 1]);
        float o2 = Y[j][2] + gelu_t(G[j][2] + prm[256 + col]);
        float o3 = Y[j][3] + gelu_t(G[j][3] + prm[256 + col + 1]);
        if (tg0 < T_out) *(float2*)&ob[(size_t)tg0 * C + col] = make_float2(o0, o1);
        if (tg1 < T_out) *(float2*)&ob[(size_t)tg1 * C + col] = make_float2(o2, o3);
    }
}

#define SMEM_NS1 (((TILE + 6) * RST + 2 * 4 * 2048 + 256 + 384) * 4)
#define SMEM_NS2 (((2 * TILE + 12) * RST + 2 * 2 * 2048 + 256 + 384) * 4)

// ---------------- end: zf = z @ end_k + end_b ----------------
__global__ void end_kernel(const float* __restrict__ z, const float* __restrict__ ek,
                           const float* __restrict__ eb, float* __restrict__ zf, int Tf) {
    int warp = (blockIdx.x * blockDim.x + threadIdx.x) >> 5;
    int lane = threadIdx.x & 31;
    if (warp >= Bz * Tf) return;
    float4 v = ((const float4*)(z + (size_t)warp * C))[lane];
    float4 e = ((const float4*)ek)[lane];
    float s = v.x * e.x + v.y * e.y + v.z * e.z + v.w * e.w;
#pragma unroll
    for (int o = 16; o >= 1; o >>= 1) s += __shfl_xor_sync(0xffffffffu, s, o);
    if (lane == 0) zf[warp] = s + eb[0];
}

// ---------------- final output assembly ----------------
__global__ void final_kernel(const float* __restrict__ foundry, const float* __restrict__ zf,
                             float* __restrict__ out, int out_size, int Tf) {
    int idx = blockIdx.x * blockDim.x + threadIdx.x;
    if (idx >= out_size) return;
    if (idx < Bz * S0) {
        int b = idx >> 13, t = idx & (S0 - 1);
        out[idx] = (t < S0 - 1) ? foundry[(b << 13) + t + 1] : zf[b * Tf + (Tf - 1)];
    } else if (idx < Bz * S0 + Bz * Tf) {
        out[idx] = zf[idx - Bz * S0];
    } else {
        out[idx] = 0.0f;
    }
}

extern "C" void kernel_launch(void* const* d_in, const int* in_sizes, int n_in,
                              void* d_out, int out_size) {
    const float* foundry = (const float*)d_in[0];
    const float* ipt     = (const float*)d_in[1];
    const float* start_k = (const float*)d_in[2];
    const float* start_b = (const float*)d_in[3];
    const float* w_dyn   = (const float*)d_in[4];
    const float* ln_s    = (const float*)d_in[5];
    const float* ln_b    = (const float*)d_in[6];
    const float* pw_k    = (const float*)d_in[7];
    const float* pw_b    = (const float*)d_in[8];
    const float* end_k   = (const float*)d_in[9];
    const float* end_b   = (const float*)d_in[10];
    float* out = (float*)d_out;

    float *pA, *pB, *pZ;
    unsigned *pW, *pP;
    cudaGetSymbolAddress((void**)&pA, g_bufA);
    cudaGetSymbolAddress((void**)&pB, g_bufB);
    cudaGetSymbolAddress((void**)&pW, g_whl);
    cudaGetSymbolAddress((void**)&pP, g_phl);
    cudaGetSymbolAddress((void**)&pZ, g_zf);

    cudaFuncSetAttribute(conv_tpl<1>, cudaFuncAttributeMaxDynamicSharedMemorySize, SMEM_NS1);
    cudaFuncSetAttribute(conv_tpl<2>, cudaFuncAttributeMaxDynamicSharedMemorySize, SMEM_NS2);

    split_wd_kernel<<<(DEPTH * Kc * 8 * 128 * 4 + 255) / 256, 256>>>(w_dyn, (uint4*)pW);
    split_pk_kernel<<<(DEPTH * 8 * 128 * 4 + 255) / 256, 256>>>(pw_k, (uint4*)pP);
    start_kernel<<<(Bz * S0 * C) / 256, 256>>>(ipt, start_k, start_b, pA);

    // block 0: stride-2 target block, 8192 -> 4090
    int T = S0;
    int T2 = (S0 - 2 * Kc) / 2 + 1;   // 4090
    conv_tpl<2><<<dim3((T2 + TILE - 1) / TILE, Bz), 256, SMEM_NS2>>>(
        pA, pB, T, T2, pW, ln_s, ln_b, pP, pw_b);

    float* src = pB;
    float* dst = pA;
    int Tc = T2;
    for (int i = 1; i < DEPTH; i++) {
        int To = Tc - (Kc - 1);
        conv_tpl<1><<<dim3((To + TILE - 1) / TILE, Bz), 256, SMEM_NS1>>>(
            src, dst, Tc, To,
            pW + (size_t)i * Kc * 8 * 128 * 16,
            ln_s + i * C, ln_b + i * C,
            pP + (size_t)i * 8 * 128 * 16, pw_b + i * C);
        float* tmp = src; src = dst; dst = tmp;
        Tc = To;
    }

    int warps = Bz * Tc;
    end_kernel<<<(warps * 32 + 255) / 256, 256>>>(src, end_k, end_b, pZ, Tc);
    final_kernel<<<(out_size + 255) / 256, 256>>>(foundry, pZ, out, out_size, Tc);
}